// round 7
// baseline (speedup 1.0000x reference)
#include <cuda_runtime.h>
#include <math.h>

#define LSEQ 2048
#define DMODEL 2048
#define NH 16
#define NKVH 4
#define HDIM 128
#define NE 16
#define NTOPK 4
#define NG 4
#define NTKG 2
#define EI 1024
#define SHI 2048
#define NT 2048
#define EPSV 1e-5f
#define ATTN_SCALE 0.08838834764831845f
#define RSF 2.5f

// ---------------- scratch ----------------
__device__ float g_h   [LSEQ*DMODEL];
__device__ float g_q   [LSEQ*NH*HDIM];
__device__ float g_k   [LSEQ*NKVH*HDIM];
__device__ float g_v   [LSEQ*NKVH*HDIM];
__device__ float g_attn[LSEQ*NH*HDIM];
__device__ float g_h1  [LSEQ*DMODEL];
__device__ float g_t   [LSEQ*DMODEL];
__device__ float g_Cw  [NT*NE];
__device__ int   g_cnt [NE];
__device__ int   g_bucket[NE*NT];
__device__ float g_eg  [(size_t)NE*NT*EI];   // expert gate (then combined hm)
__device__ float g_eu  [(size_t)NE*NT*EI];   // expert up
__device__ float g_sg  [(size_t)NT*SHI];     // shared gate (then combined)
__device__ float g_su  [(size_t)NT*SHI];     // shared up
__device__ float g_y   [(size_t)NT*DMODEL];
__device__ float g_cos [LSEQ*64];
__device__ float g_sin [LSEQ*64];

// ---------------- helpers ----------------
__device__ __forceinline__ unsigned f2tf(float f){
    unsigned u; asm("cvt.rna.tf32.f32 %0,%1;" : "=r"(u) : "f"(f)); return u;
}
__device__ __forceinline__ void mma_tf32(float c[4],
    unsigned a0, unsigned a1, unsigned a2, unsigned a3, unsigned b0, unsigned b1)
{
    asm volatile("mma.sync.aligned.m16n8k8.row.col.f32.tf32.tf32.f32 "
        "{%0,%1,%2,%3},{%4,%5,%6,%7},{%8,%9},{%0,%1,%2,%3};"
        : "+f"(c[0]), "+f"(c[1]), "+f"(c[2]), "+f"(c[3])
        : "r"(a0), "r"(a1), "r"(a2), "r"(a3), "r"(b0), "r"(b1));
}

// ---------------- RoPE table (double-precision trig, fast-math-immune) ----------------
__global__ void rope_table_kernel()
{
    int pos = blockIdx.x, j = threadIdx.x;
    float p    = (float)pow(1000000.0, (double)j / 64.0);
    float freq = 1.0f / p;
    float ang  = (float)pos * freq;
    double sd, cd; sincos((double)ang, &sd, &cd);
    g_cos[pos * 64 + j] = (float)cd;
    g_sin[pos * 64 + j] = (float)sd;
}

// ---------------- RMSNorm ----------------
__global__ __launch_bounds__(256) void rmsnorm_kernel(const float* __restrict__ x,
                                                      const float* __restrict__ w,
                                                      float* __restrict__ out)
{
    int row = blockIdx.x;
    const float* xr = x + (size_t)row * DMODEL;
    float ss = 0.f;
    for (int d = threadIdx.x; d < DMODEL; d += 256) { float v = xr[d]; ss += v * v; }
    __shared__ float red[8];
    #pragma unroll
    for (int off = 16; off; off >>= 1) ss += __shfl_xor_sync(0xffffffffu, ss, off);
    if ((threadIdx.x & 31) == 0) red[threadIdx.x >> 5] = ss;
    __syncthreads();
    __shared__ float sinv;
    if (threadIdx.x == 0) {
        float tot = 0.f;
        #pragma unroll
        for (int i = 0; i < 8; i++) tot += red[i];
        sinv = 1.f / sqrtf(tot / (float)DMODEL + EPSV);
    }
    __syncthreads();
    float si = sinv;
    for (int d = threadIdx.x; d < DMODEL; d += 256)
        out[(size_t)row * DMODEL + d] = xr[d] * si * w[d];
}

// ---------------- per-(token,head) RMSNorm + RoPE ----------------
__global__ __launch_bounds__(128) void qknorm_rope_kernel(float* __restrict__ buf,
                                                          const float* __restrict__ w,
                                                          int nh)
{
    int row = blockIdx.x;
    int pos = row / nh;
    float* p = buf + (size_t)row * HDIM;
    int tid = threadIdx.x;
    float v = p[tid];
    float ss = v * v;
    #pragma unroll
    for (int off = 16; off; off >>= 1) ss += __shfl_xor_sync(0xffffffffu, ss, off);
    __shared__ float red[4];
    if ((tid & 31) == 0) red[tid >> 5] = ss;
    __syncthreads();
    __shared__ float sinv;
    if (tid == 0) sinv = 1.f / sqrtf((red[0] + red[1] + red[2] + red[3]) / (float)HDIM + EPSV);
    __shared__ float shn[HDIM];
    __syncthreads();
    shn[tid] = v * sinv * w[tid];
    __syncthreads();
    if (tid < 64) {
        float x1 = shn[tid], x2 = shn[tid + 64];
        float c = g_cos[pos * 64 + tid], s = g_sin[pos * 64 + tid];
        p[tid]      = x1 * c - x2 * s;
        p[tid + 64] = x2 * c + x1 * s;
    }
}

// ============ 3xTF32 dense GEMM (fp32-grade): C[M,N] = A[M,K]@B[N,K]^T ============
// 128x128 tile, BK=16, 8 warps (2x4), warp tile 64x32. MODE: 0 store, 1 store+R.
template<int MODE>
__global__ __launch_bounds__(256) void gemm3_kernel(const float* __restrict__ A,
    const float* __restrict__ B, float* __restrict__ C, const float* __restrict__ R,
    int M, int N, int K)
{
    __shared__ unsigned AsH[128][20], AsL[128][20], BsH[128][20], BsL[128][20];
    int tid = threadIdx.x, lane = tid & 31, warp = tid >> 5;
    int m0 = blockIdx.y * 128, n0 = blockIdx.x * 128;
    int wm = (warp & 1) * 64, wn = (warp >> 1) * 32;
    float acc[4][4][4] = {};
    int lr = tid >> 1, lf = (tid & 1) * 8;
    int r = lane >> 2, c = lane & 3;
    for (int k0 = 0; k0 < K; k0 += 16) {
        float4 a1 = *(const float4*)(A + (size_t)(m0 + lr) * K + k0 + lf);
        float4 a2 = *(const float4*)(A + (size_t)(m0 + lr) * K + k0 + lf + 4);
        float4 b1 = *(const float4*)(B + (size_t)(n0 + lr) * K + k0 + lf);
        float4 b2 = *(const float4*)(B + (size_t)(n0 + lr) * K + k0 + lf + 4);
        float av[8] = {a1.x,a1.y,a1.z,a1.w,a2.x,a2.y,a2.z,a2.w};
        float bv[8] = {b1.x,b1.y,b1.z,b1.w,b2.x,b2.y,b2.z,b2.w};
        #pragma unroll
        for (int i = 0; i < 8; i++) {
            unsigned h = f2tf(av[i]);
            AsH[lr][lf+i] = h; AsL[lr][lf+i] = f2tf(av[i] - __uint_as_float(h));
            unsigned g = f2tf(bv[i]);
            BsH[lr][lf+i] = g; BsL[lr][lf+i] = f2tf(bv[i] - __uint_as_float(g));
        }
        __syncthreads();
        #pragma unroll
        for (int ks = 0; ks < 16; ks += 8) {
            unsigned aH[4][4], aL[4][4], bH[4][2], bL[4][2];
            #pragma unroll
            for (int mt = 0; mt < 4; mt++) {
                int mm = wm + mt * 16;
                aH[mt][0]=AsH[mm+r][ks+c];   aH[mt][1]=AsH[mm+r+8][ks+c];
                aH[mt][2]=AsH[mm+r][ks+c+4]; aH[mt][3]=AsH[mm+r+8][ks+c+4];
                aL[mt][0]=AsL[mm+r][ks+c];   aL[mt][1]=AsL[mm+r+8][ks+c];
                aL[mt][2]=AsL[mm+r][ks+c+4]; aL[mt][3]=AsL[mm+r+8][ks+c+4];
            }
            #pragma unroll
            for (int nt = 0; nt < 4; nt++) {
                int nn = wn + nt * 8;
                bH[nt][0]=BsH[nn+r][ks+c]; bH[nt][1]=BsH[nn+r][ks+c+4];
                bL[nt][0]=BsL[nn+r][ks+c]; bL[nt][1]=BsL[nn+r][ks+c+4];
            }
            #pragma unroll
            for (int mt = 0; mt < 4; mt++)
                #pragma unroll
                for (int nt = 0; nt < 4; nt++) {
                    mma_tf32(acc[mt][nt], aH[mt][0],aH[mt][1],aH[mt][2],aH[mt][3], bH[nt][0],bH[nt][1]);
                    mma_tf32(acc[mt][nt], aL[mt][0],aL[mt][1],aL[mt][2],aL[mt][3], bH[nt][0],bH[nt][1]);
                    mma_tf32(acc[mt][nt], aH[mt][0],aH[mt][1],aH[mt][2],aH[mt][3], bL[nt][0],bL[nt][1]);
                }
        }
        __syncthreads();
    }
    int c2 = (lane & 3) * 2;
    #pragma unroll
    for (int mt = 0; mt < 4; mt++) {
        int mrow = m0 + wm + mt * 16 + r;
        #pragma unroll
        for (int nt = 0; nt < 4; nt++) {
            int ncol = n0 + wn + nt * 8 + c2;
            size_t i00 = (size_t)mrow * N + ncol;
            size_t i10 = (size_t)(mrow + 8) * N + ncol;
            if (MODE == 0) {
                C[i00] = acc[mt][nt][0]; C[i00+1] = acc[mt][nt][1];
                C[i10] = acc[mt][nt][2]; C[i10+1] = acc[mt][nt][3];
            } else {
                C[i00] = acc[mt][nt][0] + R[i00]; C[i00+1] = acc[mt][nt][1] + R[i00+1];
                C[i10] = acc[mt][nt][2] + R[i10]; C[i10+1] = acc[mt][nt][3] + R[i10+1];
            }
        }
    }
}

// ============ 1xTF32 dense GEMM: C[M,N] = A[M,K]@B[N,K]^T (store) ============
__global__ __launch_bounds__(256) void gemm1_kernel(const float* __restrict__ A,
    const float* __restrict__ B, float* __restrict__ C, int M, int N, int K)
{
    __shared__ unsigned AsH[128][20], BsH[128][20];
    int tid = threadIdx.x, lane = tid & 31, warp = tid >> 5;
    int m0 = blockIdx.y * 128, n0 = blockIdx.x * 128;
    int wm = (warp & 1) * 64, wn = (warp >> 1) * 32;
    float acc[4][4][4] = {};
    int lr = tid >> 1, lf = (tid & 1) * 8;
    int r = lane >> 2, c = lane & 3;
    for (int k0 = 0; k0 < K; k0 += 16) {
        float4 a1 = *(const float4*)(A + (size_t)(m0 + lr) * K + k0 + lf);
        float4 a2 = *(const float4*)(A + (size_t)(m0 + lr) * K + k0 + lf + 4);
        float4 b1 = *(const float4*)(B + (size_t)(n0 + lr) * K + k0 + lf);
        float4 b2 = *(const float4*)(B + (size_t)(n0 + lr) * K + k0 + lf + 4);
        float av[8] = {a1.x,a1.y,a1.z,a1.w,a2.x,a2.y,a2.z,a2.w};
        float bv[8] = {b1.x,b1.y,b1.z,b1.w,b2.x,b2.y,b2.z,b2.w};
        #pragma unroll
        for (int i = 0; i < 8; i++) {
            AsH[lr][lf+i] = f2tf(av[i]);
            BsH[lr][lf+i] = f2tf(bv[i]);
        }
        __syncthreads();
        #pragma unroll
        for (int ks = 0; ks < 16; ks += 8) {
            unsigned aH[4][4], bH[4][2];
            #pragma unroll
            for (int mt = 0; mt < 4; mt++) {
                int mm = wm + mt * 16;
                aH[mt][0]=AsH[mm+r][ks+c];   aH[mt][1]=AsH[mm+r+8][ks+c];
                aH[mt][2]=AsH[mm+r][ks+c+4]; aH[mt][3]=AsH[mm+r+8][ks+c+4];
            }
            #pragma unroll
            for (int nt = 0; nt < 4; nt++) {
                int nn = wn + nt * 8;
                bH[nt][0]=BsH[nn+r][ks+c]; bH[nt][1]=BsH[nn+r][ks+c+4];
            }
            #pragma unroll
            for (int mt = 0; mt < 4; mt++)
                #pragma unroll
                for (int nt = 0; nt < 4; nt++)
                    mma_tf32(acc[mt][nt], aH[mt][0],aH[mt][1],aH[mt][2],aH[mt][3], bH[nt][0],bH[nt][1]);
        }
        __syncthreads();
    }
    int c2 = (lane & 3) * 2;
    #pragma unroll
    for (int mt = 0; mt < 4; mt++) {
        int mrow = m0 + wm + mt * 16 + r;
        #pragma unroll
        for (int nt = 0; nt < 4; nt++) {
            int ncol = n0 + wn + nt * 8 + c2;
            size_t i00 = (size_t)mrow * N + ncol;
            size_t i10 = (size_t)(mrow + 8) * N + ncol;
            C[i00] = acc[mt][nt][0]; C[i00+1] = acc[mt][nt][1];
            C[i10] = acc[mt][nt][2]; C[i10+1] = acc[mt][nt][3];
        }
    }
}

// ============ gathered expert gate/up GEMM (1xTF32): rows = bucket tokens ============
__global__ __launch_bounds__(256) void egemm_gu_kernel(const float* __restrict__ W,
                                                       float* __restrict__ Cout)
{
    int e = blockIdx.z;
    int cnt = g_cnt[e];
    int m0 = blockIdx.y * 128;
    if (m0 >= cnt) return;
    int n0 = blockIdx.x * 128;
    __shared__ unsigned AsH[128][20], BsH[128][20];
    __shared__ int toks[128];
    int tid = threadIdx.x, lane = tid & 31, warp = tid >> 5;
    if (tid < 128) {
        int m = m0 + tid;
        toks[tid] = (m < cnt) ? g_bucket[e * NT + m] : -1;
    }
    __syncthreads();
    const float* Be = W + (size_t)e * EI * DMODEL;
    int wm = (warp & 1) * 64, wn = (warp >> 1) * 32;
    float acc[4][4][4] = {};
    int lr = tid >> 1, lf = (tid & 1) * 8;
    int r = lane >> 2, c = lane & 3;
    int mytok = toks[lr];
    const float* Arow = g_t + (size_t)(mytok >= 0 ? mytok : 0) * DMODEL;
    bool aok = (mytok >= 0);
    for (int k0 = 0; k0 < DMODEL; k0 += 16) {
        float av[8] = {};
        if (aok) {
            float4 a1 = *(const float4*)(Arow + k0 + lf);
            float4 a2 = *(const float4*)(Arow + k0 + lf + 4);
            av[0]=a1.x; av[1]=a1.y; av[2]=a1.z; av[3]=a1.w;
            av[4]=a2.x; av[5]=a2.y; av[6]=a2.z; av[7]=a2.w;
        }
        float4 b1 = *(const float4*)(Be + (size_t)(n0 + lr) * DMODEL + k0 + lf);
        float4 b2 = *(const float4*)(Be + (size_t)(n0 + lr) * DMODEL + k0 + lf + 4);
        float bv[8] = {b1.x,b1.y,b1.z,b1.w,b2.x,b2.y,b2.z,b2.w};
        #pragma unroll
        for (int i = 0; i < 8; i++) {
            AsH[lr][lf+i] = f2tf(av[i]);
            BsH[lr][lf+i] = f2tf(bv[i]);
        }
        __syncthreads();
        #pragma unroll
        for (int ks = 0; ks < 16; ks += 8) {
            unsigned aH[4][4], bH[4][2];
            #pragma unroll
            for (int mt = 0; mt < 4; mt++) {
                int mm = wm + mt * 16;
                aH[mt][0]=AsH[mm+r][ks+c];   aH[mt][1]=AsH[mm+r+8][ks+c];
                aH[mt][2]=AsH[mm+r][ks+c+4]; aH[mt][3]=AsH[mm+r+8][ks+c+4];
            }
            #pragma unroll
            for (int nt = 0; nt < 4; nt++) {
                int nn = wn + nt * 8;
                bH[nt][0]=BsH[nn+r][ks+c]; bH[nt][1]=BsH[nn+r][ks+c+4];
            }
            #pragma unroll
            for (int mt = 0; mt < 4; mt++)
                #pragma unroll
                for (int nt = 0; nt < 4; nt++)
                    mma_tf32(acc[mt][nt], aH[mt][0],aH[mt][1],aH[mt][2],aH[mt][3], bH[nt][0],bH[nt][1]);
        }
        __syncthreads();
    }
    int c2 = (lane & 3) * 2;
    #pragma unroll
    for (int mt = 0; mt < 4; mt++) {
        int mloc = wm + mt * 16 + r;
        int m = m0 + mloc;
        #pragma unroll
        for (int nt = 0; nt < 4; nt++) {
            int ncol = n0 + wn + nt * 8 + c2;
            if (m < cnt) {
                size_t i00 = ((size_t)e * NT + m) * EI + ncol;
                Cout[i00] = acc[mt][nt][0]; Cout[i00+1] = acc[mt][nt][1];
            }
            if (m + 8 < cnt) {
                size_t i10 = ((size_t)e * NT + m + 8) * EI + ncol;
                Cout[i10] = acc[mt][nt][2]; Cout[i10+1] = acc[mt][nt][3];
            }
        }
    }
}

// ============ expert down GEMM (1xTF32) + scatter atomicAdd into y ============
__global__ __launch_bounds__(256) void egemm_down_kernel(const float* __restrict__ wd)
{
    int e = blockIdx.z;
    int cnt = g_cnt[e];
    int m0 = blockIdx.y * 128;
    if (m0 >= cnt) return;
    int n0 = blockIdx.x * 128;
    __shared__ unsigned AsH[128][20], BsH[128][20];
    __shared__ int toks[128];
    int tid = threadIdx.x, lane = tid & 31, warp = tid >> 5;
    if (tid < 128) {
        int m = m0 + tid;
        toks[tid] = (m < cnt) ? g_bucket[e * NT + m] : -1;
    }
    __syncthreads();
    const float* Ae = g_eg + ((size_t)e * NT + m0) * EI;
    const float* Be = wd + (size_t)e * DMODEL * EI;
    int wm = (warp & 1) * 64, wn = (warp >> 1) * 32;
    float acc[4][4][4] = {};
    int lr = tid >> 1, lf = (tid & 1) * 8;
    int r = lane >> 2, c = lane & 3;
    bool aok = (m0 + lr) < cnt;
    for (int k0 = 0; k0 < EI; k0 += 16) {
        float av[8] = {};
        if (aok) {
            float4 a1 = *(const float4*)(Ae + (size_t)lr * EI + k0 + lf);
            float4 a2 = *(const float4*)(Ae + (size_t)lr * EI + k0 + lf + 4);
            av[0]=a1.x; av[1]=a1.y; av[2]=a1.z; av[3]=a1.w;
            av[4]=a2.x; av[5]=a2.y; av[6]=a2.z; av[7]=a2.w;
        }
        float4 b1 = *(const float4*)(Be + (size_t)(n0 + lr) * EI + k0 + lf);
        float4 b2 = *(const float4*)(Be + (size_t)(n0 + lr) * EI + k0 + lf + 4);
        float bv[8] = {b1.x,b1.y,b1.z,b1.w,b2.x,b2.y,b2.z,b2.w};
        #pragma unroll
        for (int i = 0; i < 8; i++) {
            AsH[lr][lf+i] = f2tf(av[i]);
            BsH[lr][lf+i] = f2tf(bv[i]);
        }
        __syncthreads();
        #pragma unroll
        for (int ks = 0; ks < 16; ks += 8) {
            unsigned aH[4][4], bH[4][2];
            #pragma unroll
            for (int mt = 0; mt < 4; mt++) {
                int mm = wm + mt * 16;
                aH[mt][0]=AsH[mm+r][ks+c];   aH[mt][1]=AsH[mm+r+8][ks+c];
                aH[mt][2]=AsH[mm+r][ks+c+4]; aH[mt][3]=AsH[mm+r+8][ks+c+4];
            }
            #pragma unroll
            for (int nt = 0; nt < 4; nt++) {
                int nn = wn + nt * 8;
                bH[nt][0]=BsH[nn+r][ks+c]; bH[nt][1]=BsH[nn+r][ks+c+4];
            }
            #pragma unroll
            for (int mt = 0; mt < 4; mt++)
                #pragma unroll
                for (int nt = 0; nt < 4; nt++)
                    mma_tf32(acc[mt][nt], aH[mt][0],aH[mt][1],aH[mt][2],aH[mt][3], bH[nt][0],bH[nt][1]);
        }
        __syncthreads();
    }
    int c2 = (lane & 3) * 2;
    #pragma unroll
    for (int mt = 0; mt < 4; mt++) {
        int mloc = wm + mt * 16 + r;
        #pragma unroll
        for (int nt = 0; nt < 4; nt++) {
            int ncol = n0 + wn + nt * 8 + c2;
            if (m0 + mloc < cnt) {
                int tok = toks[mloc];
                atomicAdd(&g_y[(size_t)tok * DMODEL + ncol],     acc[mt][nt][0]);
                atomicAdd(&g_y[(size_t)tok * DMODEL + ncol + 1], acc[mt][nt][1]);
            }
            if (m0 + mloc + 8 < cnt) {
                int tok = toks[mloc + 8];
                atomicAdd(&g_y[(size_t)tok * DMODEL + ncol],     acc[mt][nt][2]);
                atomicAdd(&g_y[(size_t)tok * DMODEL + ncol + 1], acc[mt][nt][3]);
            }
        }
    }
}

// ---------------- flash attention (fp32, causal, GQA) ----------------
__global__ __launch_bounds__(128) void attn_kernel()
{
    __shared__ __align__(16) float Qs[32][HDIM];
    __shared__ __align__(16) float Ks[32][HDIM];
    __shared__ __align__(16) float Vs[32][HDIM];
    int h = blockIdx.y;
    int q0 = blockIdx.x * 32;
    int kvh = h >> 2;
    int tid = threadIdx.x;
    int r = tid >> 2, qd = tid & 3;

    for (int i = tid; i < 32 * HDIM; i += 128) {
        int row = i >> 7, d = i & 127;
        Qs[row][d] = g_q[(size_t)(q0 + row) * (NH * HDIM) + h * HDIM + d];
    }
    __syncthreads();
    float qreg[32];
    #pragma unroll
    for (int d = 0; d < 32; d++) qreg[d] = Qs[r][qd * 32 + d];

    float o[32];
    #pragma unroll
    for (int d = 0; d < 32; d++) o[d] = 0.f;
    float mrow = -INFINITY, lrow = 0.f;

    for (int k0 = 0; k0 <= q0; k0 += 32) {
        __syncthreads();
        for (int i = tid; i < 32 * HDIM; i += 128) {
            int row = i >> 7, d = i & 127;
            size_t base = (size_t)(k0 + row) * (NKVH * HDIM) + kvh * HDIM + d;
            Ks[row][d] = g_k[base];
            Vs[row][d] = g_v[base];
        }
        __syncthreads();

        float s[32];
        float tmax = -INFINITY;
        #pragma unroll
        for (int j = 0; j < 32; j++) {
            float pacc = 0.f;
            const float4* K4 = (const float4*)&Ks[j][qd * 32];
            #pragma unroll
            for (int d4 = 0; d4 < 8; d4++) {
                float4 kk = K4[d4];
                pacc += qreg[d4*4+0]*kk.x + qreg[d4*4+1]*kk.y
                      + qreg[d4*4+2]*kk.z + qreg[d4*4+3]*kk.w;
            }
            pacc += __shfl_xor_sync(0xffffffffu, pacc, 1);
            pacc += __shfl_xor_sync(0xffffffffu, pacc, 2);
            pacc *= ATTN_SCALE;
            if (k0 + j > q0 + r) pacc = -INFINITY;
            s[j] = pacc;
            tmax = fmaxf(tmax, pacc);
        }
        float mnew = fmaxf(mrow, tmax);
        float alpha = __expf(mrow - mnew);
        lrow *= alpha;
        #pragma unroll
        for (int d = 0; d < 32; d++) o[d] *= alpha;
        #pragma unroll
        for (int j = 0; j < 32; j++) {
            float pv = __expf(s[j] - mnew);
            lrow += pv;
            const float4* V4 = (const float4*)&Vs[j][qd * 32];
            #pragma unroll
            for (int d4 = 0; d4 < 8; d4++) {
                float4 vv = V4[d4];
                o[d4*4+0] += pv * vv.x; o[d4*4+1] += pv * vv.y;
                o[d4*4+2] += pv * vv.z; o[d4*4+3] += pv * vv.w;
            }
        }
        mrow = mnew;
    }
    float inv = 1.f / lrow;
    size_t base = (size_t)(q0 + r) * (NH * HDIM) + h * HDIM + qd * 32;
    #pragma unroll
    for (int d = 0; d < 32; d++) g_attn[base + d] = o[d] * inv;
}

// ---------------- zero expert counters ----------------
__global__ void zero_cnt_kernel()
{
    if (threadIdx.x < NE) g_cnt[threadIdx.x] = 0;
}

// ---------------- gating / routing (fp32, exact) ----------------
__global__ __launch_bounds__(256) void gate_kernel(const float* __restrict__ gate_w,
                                                   const float* __restrict__ gate_bias)
{
    int t = blockIdx.x;
    const float* tr = g_t + (size_t)t * DMODEL;
    float acc[NE];
    #pragma unroll
    for (int e = 0; e < NE; e++) acc[e] = 0.f;
    for (int d = threadIdx.x; d < DMODEL; d += 256) {
        float xv = tr[d];
        #pragma unroll
        for (int e = 0; e < NE; e++) acc[e] += xv * gate_w[e * DMODEL + d];
    }
    __shared__ float red[NE * 8];
    int lane = threadIdx.x & 31, wid = threadIdx.x >> 5;
    #pragma unroll
    for (int e = 0; e < NE; e++) {
        float v = acc[e];
        #pragma unroll
        for (int off = 16; off; off >>= 1) v += __shfl_xor_sync(0xffffffffu, v, off);
        if (lane == 0) red[e * 8 + wid] = v;
    }
    __syncthreads();
    __shared__ float sc_s[NE];
    if (threadIdx.x < NE) {
        float sum = 0.f;
        #pragma unroll
        for (int wq = 0; wq < 8; wq++) sum += red[threadIdx.x * 8 + wq];
        sc_s[threadIdx.x] = 1.f / (1.f + expf(-sum));
    }
    __syncthreads();
    if (threadIdx.x == 0) {
        float sc[NE], s2[NE];
        #pragma unroll
        for (int e = 0; e < NE; e++) { sc[e] = sc_s[e]; s2[e] = sc[e] + gate_bias[e]; }
        float gs[NG];
        #pragma unroll
        for (int gq = 0; gq < NG; gq++) {
            float m1 = -INFINITY, m2 = -INFINITY;
            #pragma unroll
            for (int j = 0; j < NE / NG; j++) {
                float vv = s2[gq * (NE / NG) + j];
                if (vv > m1) { m2 = m1; m1 = vv; }
                else if (vv > m2) { m2 = vv; }
            }
            gs[gq] = m1 + m2;
        }
        bool gsel[NG] = {false, false, false, false};
        {
            float gtmp[NG];
            #pragma unroll
            for (int gq = 0; gq < NG; gq++) gtmp[gq] = gs[gq];
            for (int it = 0; it < NTKG; it++) {
                int bi = 0; float bv = -INFINITY;
                #pragma unroll
                for (int gq = 0; gq < NG; gq++)
                    if (gtmp[gq] > bv) { bv = gtmp[gq]; bi = gq; }
                gsel[bi] = true; gtmp[bi] = -INFINITY;
            }
        }
        float masked[NE];
        #pragma unroll
        for (int e = 0; e < NE; e++) masked[e] = gsel[e >> 2] ? s2[e] : 0.f;
        int inds[NTOPK];
        for (int it = 0; it < NTOPK; it++) {
            int bi = 0; float bv = -INFINITY;
            #pragma unroll
            for (int e = 0; e < NE; e++)
                if (masked[e] > bv) { bv = masked[e]; bi = e; }
            inds[it] = bi; masked[bi] = -INFINITY;
        }
        float wv[NTOPK], wsum = 0.f;
        #pragma unroll
        for (int i = 0; i < NTOPK; i++) { wv[i] = sc[inds[i]]; wsum += wv[i]; }
        float invw = RSF / (wsum + 1e-20f);
        float crow[NE];
        #pragma unroll
        for (int e = 0; e < NE; e++) crow[e] = 0.f;
        #pragma unroll
        for (int i = 0; i < NTOPK; i++) crow[inds[i]] += wv[i] * invw;
        #pragma unroll
        for (int e = 0; e < NE; e++) g_Cw[t * NE + e] = crow[e];
        #pragma unroll
        for (int i = 0; i < NTOPK; i++) {
            int e = inds[i];
            int posn = atomicAdd(&g_cnt[e], 1);
            g_bucket[e * NT + posn] = t;
        }
    }
}

// ---------------- elementwise combines ----------------
__global__ __launch_bounds__(256) void combine_expert_kernel()
{
    int e = blockIdx.y;
    int cnt = g_cnt[e];
    size_t idx = (size_t)blockIdx.x * 256 + threadIdx.x;
    int m = (int)(idx / EI);
    if (m >= cnt) return;
    int tok = g_bucket[e * NT + m];
    float w = g_Cw[tok * NE + e];
    size_t o = ((size_t)e * NT + m) * EI + (idx % EI);
    float gv = g_eg[o], uv = g_eu[o];
    g_eg[o] = (gv / (1.f + expf(-gv))) * uv * w;
}

__global__ __launch_bounds__(256) void combine_shared_kernel()
{
    size_t idx = (size_t)blockIdx.x * 256 + threadIdx.x;
    if (idx >= (size_t)NT * SHI) return;
    float gv = g_sg[idx], uv = g_su[idx];
    g_sg[idx] = (gv / (1.f + expf(-gv))) * uv;
}

// ---------------- final: out = h1 + y ----------------
__global__ void final_add_kernel(float* __restrict__ out)
{
    int i = blockIdx.x * blockDim.x + threadIdx.x;
    if (i < NT * DMODEL) out[i] = g_h1[i] + g_y[i];
}

// ---------------- launch ----------------
extern "C" void kernel_launch(void* const* d_in, const int* in_sizes, int n_in,
                              void* d_out, int out_size)
{
    const float* x        = (const float*)d_in[0];
    const float* w_q      = (const float*)d_in[1];
    const float* w_k      = (const float*)d_in[2];
    const float* w_v      = (const float*)d_in[3];
    const float* w_o      = (const float*)d_in[4];
    const float* q_norm_w = (const float*)d_in[5];
    const float* k_norm_w = (const float*)d_in[6];
    const float* ln1_w    = (const float*)d_in[7];
    const float* ln2_w    = (const float*)d_in[8];
    const float* gate_w   = (const float*)d_in[9];
    const float* gate_b   = (const float*)d_in[10];
    const float* wg       = (const float*)d_in[11];
    const float* wu       = (const float*)d_in[12];
    const float* wd       = (const float*)d_in[13];
    const float* sh_g     = (const float*)d_in[14];
    const float* sh_u     = (const float*)d_in[15];
    const float* sh_d     = (const float*)d_in[16];
    float* out = (float*)d_out;

    float *ph, *pq, *pk, *pv, *pattn, *ph1, *pt, *peg, *peu, *psg, *psu, *py;
    cudaGetSymbolAddress((void**)&ph,    g_h);
    cudaGetSymbolAddress((void**)&pq,    g_q);
    cudaGetSymbolAddress((void**)&pk,    g_k);
    cudaGetSymbolAddress((void**)&pv,    g_v);
    cudaGetSymbolAddress((void**)&pattn, g_attn);
    cudaGetSymbolAddress((void**)&ph1,   g_h1);
    cudaGetSymbolAddress((void**)&pt,    g_t);
    cudaGetSymbolAddress((void**)&peg,   g_eg);
    cudaGetSymbolAddress((void**)&peu,   g_eu);
    cudaGetSymbolAddress((void**)&psg,   g_sg);
    cudaGetSymbolAddress((void**)&psu,   g_su);
    cudaGetSymbolAddress((void**)&py,    g_y);

    // 0. RoPE table
    rope_table_kernel<<<LSEQ, 64>>>();
    // 1. pre-attn norm
    rmsnorm_kernel<<<LSEQ, 256>>>(x, ln1_w, ph);
    // 2. QKV projections (3xTF32, fp32-grade)
    gemm3_kernel<0><<<dim3(16, 16), 256>>>(ph, w_q, pq, nullptr, LSEQ, NH * HDIM, DMODEL);
    gemm3_kernel<0><<<dim3(4, 16), 256>>>(ph, w_k, pk, nullptr, LSEQ, NKVH * HDIM, DMODEL);
    gemm3_kernel<0><<<dim3(4, 16), 256>>>(ph, w_v, pv, nullptr, LSEQ, NKVH * HDIM, DMODEL);
    // 3. q/k rmsnorm + rope
    qknorm_rope_kernel<<<LSEQ * NH, 128>>>(pq, q_norm_w, NH);
    qknorm_rope_kernel<<<LSEQ * NKVH, 128>>>(pk, k_norm_w, NKVH);
    // 4. attention (fp32)
    attn_kernel<<<dim3(LSEQ / 32, NH), 128>>>();
    // 5. output proj + residual (3xTF32)
    gemm3_kernel<1><<<dim3(16, 16), 256>>>(pattn, w_o, ph1, x, LSEQ, DMODEL, NH * HDIM);
    // 6. post-attn norm
    rmsnorm_kernel<<<LSEQ, 256>>>(ph1, ln2_w, pt);
    // 7. routing (fp32, exact)
    zero_cnt_kernel<<<1, 32>>>();
    gate_kernel<<<NT, 256>>>(gate_w, gate_b);
    // 8. shared expert (1xTF32): gate, up, combine, down (down STORES y)
    gemm1_kernel<<<dim3(SHI / 128, NT / 128), 256>>>(pt, sh_g, psg, NT, SHI, DMODEL);
    gemm1_kernel<<<dim3(SHI / 128, NT / 128), 256>>>(pt, sh_u, psu, NT, SHI, DMODEL);
    combine_shared_kernel<<<(int)(((size_t)NT * SHI + 255) / 256), 256>>>();
    gemm1_kernel<<<dim3(DMODEL / 128, NT / 128), 256>>>(psg, sh_d, py, NT, DMODEL, SHI);
    // 9. routed experts (1xTF32, gathered): gate, up, combine, down (atomicAdd y)
    egemm_gu_kernel<<<dim3(EI / 128, NT / 128, NE), 256>>>(wg, peg);
    egemm_gu_kernel<<<dim3(EI / 128, NT / 128, NE), 256>>>(wu, peu);
    combine_expert_kernel<<<dim3((int)(((size_t)NT * EI + 255) / 256), NE), 256>>>();
    egemm_down_kernel<<<dim3(DMODEL / 128, NT / 128, NE), 256>>>(wd);
    // 10. final residual add
    final_add_kernel<<<(NT * DMODEL + 255) / 256, 256>>>(out);
    (void)in_sizes; (void)n_in; (void)out_size;
}

// round 8
// speedup vs baseline: 1.2075x; 1.2075x over previous
#include <cuda_runtime.h>
#include <math.h>

#define LSEQ 2048
#define DMODEL 2048
#define NH 16
#define NKVH 4
#define HDIM 128
#define NE 16
#define NTOPK 4
#define NG 4
#define NTKG 2
#define EI 1024
#define SHI 2048
#define NT 2048
#define EPSV 1e-5f
#define ATTN_SCALE 0.08838834764831845f
#define RSF 2.5f

// smem tile geometry: 128 rows x 32 k-floats, stride 36 (conflict-free: bank=(4r+c)&31)
#define TSTRIDE 36
#define TSTAGE  (128*TSTRIDE)          // floats per stage per matrix
#define GEMM_SMEM (4*TSTAGE*4)         // bytes: 2 stages x (A+B) = 73728

// ---------------- scratch ----------------
__device__ float g_h   [LSEQ*DMODEL];
__device__ float g_q   [LSEQ*NH*HDIM];
__device__ float g_k   [LSEQ*NKVH*HDIM];
__device__ float g_v   [LSEQ*NKVH*HDIM];
__device__ float g_attn[LSEQ*NH*HDIM];
__device__ float g_h1  [LSEQ*DMODEL];
__device__ float g_t   [LSEQ*DMODEL];
__device__ float g_Cw  [NT*NE];
__device__ int   g_cnt [NE];
__device__ int   g_bucket[NE*NT];
__device__ float g_eg  [(size_t)NE*NT*EI];
__device__ float g_eu  [(size_t)NE*NT*EI];
__device__ float g_sg  [(size_t)NT*SHI];
__device__ float g_su  [(size_t)NT*SHI];
__device__ float g_y   [(size_t)NT*DMODEL];
__device__ float g_cos [LSEQ*64];
__device__ float g_sin [LSEQ*64];

// ---------------- helpers ----------------
__device__ __forceinline__ unsigned f2tf(float f){
    unsigned u; asm("cvt.rna.tf32.f32 %0,%1;" : "=r"(u) : "f"(f)); return u;
}
__device__ __forceinline__ void mma_tf32(float c[4],
    unsigned a0, unsigned a1, unsigned a2, unsigned a3, unsigned b0, unsigned b1)
{
    asm volatile("mma.sync.aligned.m16n8k8.row.col.f32.tf32.tf32.f32 "
        "{%0,%1,%2,%3},{%4,%5,%6,%7},{%8,%9},{%0,%1,%2,%3};"
        : "+f"(c[0]), "+f"(c[1]), "+f"(c[2]), "+f"(c[3])
        : "r"(a0), "r"(a1), "r"(a2), "r"(a3), "r"(b0), "r"(b1));
}
__device__ __forceinline__ unsigned sptr(const void* p){
    return (unsigned)__cvta_generic_to_shared(p);
}
#define CPA16(dst, src, n) asm volatile( \
    "cp.async.cg.shared.global [%0], [%1], 16, %2;\n" :: "r"(dst), "l"(src), "r"(n))
#define CPCOMMIT() asm volatile("cp.async.commit_group;\n" ::: "memory")
#define CPWAIT0()  asm volatile("cp.async.wait_group 0;\n" ::: "memory")

// ---------------- MMA stage compute (reads raw fp32 smem, converts at use) ----------------
__device__ __forceinline__ void mma_stage_1x(const float* As, const float* Bs,
    float (*acc)[4][4], int wm, int wn, int r, int c)
{
    #pragma unroll
    for (int ks = 0; ks < 32; ks += 8) {
        unsigned aF[4][4], bF[4][2];
        #pragma unroll
        for (int mt = 0; mt < 4; mt++) {
            const float* p = As + (wm + mt*16 + r)*TSTRIDE + ks + c;
            aF[mt][0] = f2tf(p[0]);          aF[mt][1] = f2tf(p[8*TSTRIDE]);
            aF[mt][2] = f2tf(p[4]);          aF[mt][3] = f2tf(p[8*TSTRIDE+4]);
        }
        #pragma unroll
        for (int nt = 0; nt < 4; nt++) {
            const float* p = Bs + (wn + nt*8 + r)*TSTRIDE + ks + c;
            bF[nt][0] = f2tf(p[0]);          bF[nt][1] = f2tf(p[4]);
        }
        #pragma unroll
        for (int mt = 0; mt < 4; mt++)
            #pragma unroll
            for (int nt = 0; nt < 4; nt++)
                mma_tf32(acc[mt][nt], aF[mt][0],aF[mt][1],aF[mt][2],aF[mt][3],
                         bF[nt][0],bF[nt][1]);
    }
}

__device__ __forceinline__ void mma_stage_3x(const float* As, const float* Bs,
    float (*acc)[4][4], int wm, int wn, int r, int c)
{
    #pragma unroll
    for (int ks = 0; ks < 32; ks += 8) {
        unsigned aH[4][4], aL[4][4], bH[4][2], bL[4][2];
        #pragma unroll
        for (int mt = 0; mt < 4; mt++) {
            const float* p = As + (wm + mt*16 + r)*TSTRIDE + ks + c;
            float v0 = p[0], v1 = p[8*TSTRIDE], v2 = p[4], v3 = p[8*TSTRIDE+4];
            aH[mt][0]=f2tf(v0); aL[mt][0]=f2tf(v0-__uint_as_float(aH[mt][0]));
            aH[mt][1]=f2tf(v1); aL[mt][1]=f2tf(v1-__uint_as_float(aH[mt][1]));
            aH[mt][2]=f2tf(v2); aL[mt][2]=f2tf(v2-__uint_as_float(aH[mt][2]));
            aH[mt][3]=f2tf(v3); aL[mt][3]=f2tf(v3-__uint_as_float(aH[mt][3]));
        }
        #pragma unroll
        for (int nt = 0; nt < 4; nt++) {
            const float* p = Bs + (wn + nt*8 + r)*TSTRIDE + ks + c;
            float v0 = p[0], v1 = p[4];
            bH[nt][0]=f2tf(v0); bL[nt][0]=f2tf(v0-__uint_as_float(bH[nt][0]));
            bH[nt][1]=f2tf(v1); bL[nt][1]=f2tf(v1-__uint_as_float(bH[nt][1]));
        }
        #pragma unroll
        for (int mt = 0; mt < 4; mt++)
            #pragma unroll
            for (int nt = 0; nt < 4; nt++) {
                mma_tf32(acc[mt][nt], aH[mt][0],aH[mt][1],aH[mt][2],aH[mt][3], bH[nt][0],bH[nt][1]);
                mma_tf32(acc[mt][nt], aL[mt][0],aL[mt][1],aL[mt][2],aL[mt][3], bH[nt][0],bH[nt][1]);
                mma_tf32(acc[mt][nt], aH[mt][0],aH[mt][1],aH[mt][2],aH[mt][3], bL[nt][0],bL[nt][1]);
            }
    }
}

// ============ fused QKV projection (3xTF32, pipelined) ============
__global__ __launch_bounds__(256) void qkv3_kernel(const float* __restrict__ A,
    const float* __restrict__ wq, const float* __restrict__ wk, const float* __restrict__ wv)
{
    extern __shared__ float sm[];
    float* As = sm;
    float* Bs = sm + 2*TSTAGE;
    const int K = DMODEL;
    int tid = threadIdx.x, lane = tid & 31, warp = tid >> 5;
    int m0 = blockIdx.y * 128, n0 = blockIdx.x * 128;
    int wm = (warp & 1) * 64, wn = (warp >> 1) * 32;
    int r = lane >> 2, c = lane & 3;

    const float* B; float* Cp; int ldc, ncol0;
    if (n0 < 2048)      { B = wq + (size_t)n0 * K;          Cp = g_q; ldc = NH*HDIM;   ncol0 = n0; }
    else if (n0 < 2560) { B = wk + (size_t)(n0 - 2048) * K; Cp = g_k; ldc = NKVH*HDIM; ncol0 = n0 - 2048; }
    else                { B = wv + (size_t)(n0 - 2560) * K; Cp = g_v; ldc = NKVH*HDIM; ncol0 = n0 - 2560; }

    const float* aSrc[4]; const float* bSrc[4]; int soff[4];
    #pragma unroll
    for (int i = 0; i < 4; i++) {
        int idx = tid + i * 256, row = idx >> 3, ch = idx & 7;
        soff[i] = row * TSTRIDE + ch * 4;
        aSrc[i] = A + (size_t)(m0 + row) * K + ch * 4;
        bSrc[i] = B + (size_t)row * K + ch * 4;
    }
    #pragma unroll
    for (int i = 0; i < 4; i++) {
        CPA16(sptr(As + soff[i]), aSrc[i], 16);
        CPA16(sptr(Bs + soff[i]), bSrc[i], 16);
    }
    CPCOMMIT();

    float acc[4][4][4] = {};
    for (int k0 = 0; k0 < K; k0 += 32) {
        CPWAIT0(); __syncthreads();
        int cur = (k0 >> 5) & 1, nxt = cur ^ 1;
        if (k0 + 32 < K) {
            #pragma unroll
            for (int i = 0; i < 4; i++) {
                CPA16(sptr(As + nxt*TSTAGE + soff[i]), aSrc[i] + k0 + 32, 16);
                CPA16(sptr(Bs + nxt*TSTAGE + soff[i]), bSrc[i] + k0 + 32, 16);
            }
            CPCOMMIT();
        }
        mma_stage_3x(As + cur*TSTAGE, Bs + cur*TSTAGE, acc, wm, wn, r, c);
    }
    int c2 = (lane & 3) * 2;
    #pragma unroll
    for (int mt = 0; mt < 4; mt++) {
        int mrow = m0 + wm + mt * 16 + r;
        #pragma unroll
        for (int nt = 0; nt < 4; nt++) {
            int col = ncol0 + wn + nt * 8 + c2;
            size_t i00 = (size_t)mrow * ldc + col;
            size_t i10 = (size_t)(mrow + 8) * ldc + col;
            Cp[i00] = acc[mt][nt][0]; Cp[i00+1] = acc[mt][nt][1];
            Cp[i10] = acc[mt][nt][2]; Cp[i10+1] = acc[mt][nt][3];
        }
    }
}

// ============ o-proj + residual (3xTF32, pipelined) ============
__global__ __launch_bounds__(256) void gemm3o_kernel(const float* __restrict__ A,
    const float* __restrict__ B, float* __restrict__ C, const float* __restrict__ R)
{
    extern __shared__ float sm[];
    float* As = sm;
    float* Bs = sm + 2*TSTAGE;
    const int K = NH*HDIM, N = DMODEL;
    int tid = threadIdx.x, lane = tid & 31, warp = tid >> 5;
    int m0 = blockIdx.y * 128, n0 = blockIdx.x * 128;
    int wm = (warp & 1) * 64, wn = (warp >> 1) * 32;
    int r = lane >> 2, c = lane & 3;

    const float* aSrc[4]; const float* bSrc[4]; int soff[4];
    #pragma unroll
    for (int i = 0; i < 4; i++) {
        int idx = tid + i * 256, row = idx >> 3, ch = idx & 7;
        soff[i] = row * TSTRIDE + ch * 4;
        aSrc[i] = A + (size_t)(m0 + row) * K + ch * 4;
        bSrc[i] = B + (size_t)(n0 + row) * K + ch * 4;
    }
    #pragma unroll
    for (int i = 0; i < 4; i++) {
        CPA16(sptr(As + soff[i]), aSrc[i], 16);
        CPA16(sptr(Bs + soff[i]), bSrc[i], 16);
    }
    CPCOMMIT();

    float acc[4][4][4] = {};
    for (int k0 = 0; k0 < K; k0 += 32) {
        CPWAIT0(); __syncthreads();
        int cur = (k0 >> 5) & 1, nxt = cur ^ 1;
        if (k0 + 32 < K) {
            #pragma unroll
            for (int i = 0; i < 4; i++) {
                CPA16(sptr(As + nxt*TSTAGE + soff[i]), aSrc[i] + k0 + 32, 16);
                CPA16(sptr(Bs + nxt*TSTAGE + soff[i]), bSrc[i] + k0 + 32, 16);
            }
            CPCOMMIT();
        }
        mma_stage_3x(As + cur*TSTAGE, Bs + cur*TSTAGE, acc, wm, wn, r, c);
    }
    int c2 = (lane & 3) * 2;
    #pragma unroll
    for (int mt = 0; mt < 4; mt++) {
        int mrow = m0 + wm + mt * 16 + r;
        #pragma unroll
        for (int nt = 0; nt < 4; nt++) {
            int col = n0 + wn + nt * 8 + c2;
            size_t i00 = (size_t)mrow * N + col;
            size_t i10 = (size_t)(mrow + 8) * N + col;
            C[i00] = acc[mt][nt][0] + R[i00]; C[i00+1] = acc[mt][nt][1] + R[i00+1];
            C[i10] = acc[mt][nt][2] + R[i10]; C[i10+1] = acc[mt][nt][3] + R[i10+1];
        }
    }
}

// ============ dense 1xTF32 GEMM (pipelined): C[M,N] = A[M,K]@B[N,K]^T ============
__global__ __launch_bounds__(256) void dense1_kernel(const float* __restrict__ A,
    const float* __restrict__ B, float* __restrict__ C, int N, int K)
{
    extern __shared__ float sm[];
    float* As = sm;
    float* Bs = sm + 2*TSTAGE;
    int tid = threadIdx.x, lane = tid & 31, warp = tid >> 5;
    int m0 = blockIdx.y * 128, n0 = blockIdx.x * 128;
    int wm = (warp & 1) * 64, wn = (warp >> 1) * 32;
    int r = lane >> 2, c = lane & 3;

    const float* aSrc[4]; const float* bSrc[4]; int soff[4];
    #pragma unroll
    for (int i = 0; i < 4; i++) {
        int idx = tid + i * 256, row = idx >> 3, ch = idx & 7;
        soff[i] = row * TSTRIDE + ch * 4;
        aSrc[i] = A + (size_t)(m0 + row) * K + ch * 4;
        bSrc[i] = B + (size_t)(n0 + row) * K + ch * 4;
    }
    #pragma unroll
    for (int i = 0; i < 4; i++) {
        CPA16(sptr(As + soff[i]), aSrc[i], 16);
        CPA16(sptr(Bs + soff[i]), bSrc[i], 16);
    }
    CPCOMMIT();

    float acc[4][4][4] = {};
    for (int k0 = 0; k0 < K; k0 += 32) {
        CPWAIT0(); __syncthreads();
        int cur = (k0 >> 5) & 1, nxt = cur ^ 1;
        if (k0 + 32 < K) {
            #pragma unroll
            for (int i = 0; i < 4; i++) {
                CPA16(sptr(As + nxt*TSTAGE + soff[i]), aSrc[i] + k0 + 32, 16);
                CPA16(sptr(Bs + nxt*TSTAGE + soff[i]), bSrc[i] + k0 + 32, 16);
            }
            CPCOMMIT();
        }
        mma_stage_1x(As + cur*TSTAGE, Bs + cur*TSTAGE, acc, wm, wn, r, c);
    }
    int c2 = (lane & 3) * 2;
    #pragma unroll
    for (int mt = 0; mt < 4; mt++) {
        int mrow = m0 + wm + mt * 16 + r;
        #pragma unroll
        for (int nt = 0; nt < 4; nt++) {
            int col = n0 + wn + nt * 8 + c2;
            size_t i00 = (size_t)mrow * N + col;
            size_t i10 = (size_t)(mrow + 8) * N + col;
            C[i00] = acc[mt][nt][0]; C[i00+1] = acc[mt][nt][1];
            C[i10] = acc[mt][nt][2]; C[i10+1] = acc[mt][nt][3];
        }
    }
}

// ============ gathered expert gate/up GEMM (1xTF32, pipelined) ============
__global__ __launch_bounds__(256) void egu1_kernel(const float* __restrict__ W,
                                                   float* __restrict__ Cout)
{
    int e = blockIdx.z;
    int cnt = g_cnt[e];
    int m0 = blockIdx.y * 128;
    if (m0 >= cnt) return;
    int n0 = blockIdx.x * 128;
    extern __shared__ float sm[];
    float* As = sm;
    float* Bs = sm + 2*TSTAGE;
    __shared__ int toks[128];
    const int K = DMODEL;
    int tid = threadIdx.x, lane = tid & 31, warp = tid >> 5;
    if (tid < 128) {
        int m = m0 + tid;
        toks[tid] = (m < cnt) ? g_bucket[e * NT + m] : -1;
    }
    __syncthreads();
    const float* B = W + (size_t)e * EI * DMODEL + (size_t)n0 * K;
    int wm = (warp & 1) * 64, wn = (warp >> 1) * 32;
    int r = lane >> 2, c = lane & 3;

    const float* aSrc[4]; const float* bSrc[4]; int soff[4]; int aBytes[4];
    #pragma unroll
    for (int i = 0; i < 4; i++) {
        int idx = tid + i * 256, row = idx >> 3, ch = idx & 7;
        soff[i] = row * TSTRIDE + ch * 4;
        int tok = toks[row];
        aBytes[i] = (tok >= 0) ? 16 : 0;
        aSrc[i] = g_t + (size_t)(tok >= 0 ? tok : 0) * K + ch * 4;
        bSrc[i] = B + (size_t)row * K + ch * 4;
    }
    #pragma unroll
    for (int i = 0; i < 4; i++) {
        CPA16(sptr(As + soff[i]), aSrc[i], aBytes[i]);
        CPA16(sptr(Bs + soff[i]), bSrc[i], 16);
    }
    CPCOMMIT();

    float acc[4][4][4] = {};
    for (int k0 = 0; k0 < K; k0 += 32) {
        CPWAIT0(); __syncthreads();
        int cur = (k0 >> 5) & 1, nxt = cur ^ 1;
        if (k0 + 32 < K) {
            #pragma unroll
            for (int i = 0; i < 4; i++) {
                CPA16(sptr(As + nxt*TSTAGE + soff[i]), aSrc[i] + k0 + 32, aBytes[i]);
                CPA16(sptr(Bs + nxt*TSTAGE + soff[i]), bSrc[i] + k0 + 32, 16);
            }
            CPCOMMIT();
        }
        mma_stage_1x(As + cur*TSTAGE, Bs + cur*TSTAGE, acc, wm, wn, r, c);
    }
    int c2 = (lane & 3) * 2;
    #pragma unroll
    for (int mt = 0; mt < 4; mt++) {
        int mloc = wm + mt * 16 + r;
        int m = m0 + mloc;
        #pragma unroll
        for (int nt = 0; nt < 4; nt++) {
            int col = n0 + wn + nt * 8 + c2;
            if (m < cnt) {
                size_t i00 = ((size_t)e * NT + m) * EI + col;
                Cout[i00] = acc[mt][nt][0]; Cout[i00+1] = acc[mt][nt][1];
            }
            if (m + 8 < cnt) {
                size_t i10 = ((size_t)e * NT + m + 8) * EI + col;
                Cout[i10] = acc[mt][nt][2]; Cout[i10+1] = acc[mt][nt][3];
            }
        }
    }
}

// ============ expert down GEMM (1xTF32, pipelined) + scatter atomicAdd ============
__global__ __launch_bounds__(256) void edown1_kernel(const float* __restrict__ wd)
{
    int e = blockIdx.z;
    int cnt = g_cnt[e];
    int m0 = blockIdx.y * 128;
    if (m0 >= cnt) return;
    int n0 = blockIdx.x * 128;
    extern __shared__ float sm[];
    float* As = sm;
    float* Bs = sm + 2*TSTAGE;
    __shared__ int toks[128];
    const int K = EI;
    int tid = threadIdx.x, lane = tid & 31, warp = tid >> 5;
    if (tid < 128) {
        int m = m0 + tid;
        toks[tid] = (m < cnt) ? g_bucket[e * NT + m] : -1;
    }
    __syncthreads();
    const float* Ae = g_eg + ((size_t)e * NT + m0) * EI;
    const float* B = wd + (size_t)e * DMODEL * EI + (size_t)n0 * K;
    int wm = (warp & 1) * 64, wn = (warp >> 1) * 32;
    int r = lane >> 2, c = lane & 3;

    const float* aSrc[4]; const float* bSrc[4]; int soff[4]; int aBytes[4];
    #pragma unroll
    for (int i = 0; i < 4; i++) {
        int idx = tid + i * 256, row = idx >> 3, ch = idx & 7;
        soff[i] = row * TSTRIDE + ch * 4;
        bool ok = (m0 + row) < cnt;
        aBytes[i] = ok ? 16 : 0;
        aSrc[i] = Ae + (size_t)(ok ? row : 0) * K + ch * 4;
        bSrc[i] = B + (size_t)row * K + ch * 4;
    }
    #pragma unroll
    for (int i = 0; i < 4; i++) {
        CPA16(sptr(As + soff[i]), aSrc[i], aBytes[i]);
        CPA16(sptr(Bs + soff[i]), bSrc[i], 16);
    }
    CPCOMMIT();

    float acc[4][4][4] = {};
    for (int k0 = 0; k0 < K; k0 += 32) {
        CPWAIT0(); __syncthreads();
        int cur = (k0 >> 5) & 1, nxt = cur ^ 1;
        if (k0 + 32 < K) {
            #pragma unroll
            for (int i = 0; i < 4; i++) {
                CPA16(sptr(As + nxt*TSTAGE + soff[i]), aSrc[i] + k0 + 32, aBytes[i]);
                CPA16(sptr(Bs + nxt*TSTAGE + soff[i]), bSrc[i] + k0 + 32, 16);
            }
            CPCOMMIT();
        }
        mma_stage_1x(As + cur*TSTAGE, Bs + cur*TSTAGE, acc, wm, wn, r, c);
    }
    int c2 = (lane & 3) * 2;
    #pragma unroll
    for (int mt = 0; mt < 4; mt++) {
        int mloc = wm + mt * 16 + r;
        #pragma unroll
        for (int nt = 0; nt < 4; nt++) {
            int col = n0 + wn + nt * 8 + c2;
            if (m0 + mloc < cnt) {
                int tok = toks[mloc];
                atomicAdd(&g_y[(size_t)tok * DMODEL + col],     acc[mt][nt][0]);
                atomicAdd(&g_y[(size_t)tok * DMODEL + col + 1], acc[mt][nt][1]);
            }
            if (m0 + mloc + 8 < cnt) {
                int tok = toks[mloc + 8];
                atomicAdd(&g_y[(size_t)tok * DMODEL + col],     acc[mt][nt][2]);
                atomicAdd(&g_y[(size_t)tok * DMODEL + col + 1], acc[mt][nt][3]);
            }
        }
    }
}

// ---------------- RoPE table (double-precision trig, fast-math-immune) ----------------
__global__ void rope_table_kernel()
{
    int pos = blockIdx.x, j = threadIdx.x;
    float p    = (float)pow(1000000.0, (double)j / 64.0);
    float freq = 1.0f / p;
    float ang  = (float)pos * freq;
    double sd, cd; sincos((double)ang, &sd, &cd);
    g_cos[pos * 64 + j] = (float)cd;
    g_sin[pos * 64 + j] = (float)sd;
}

// ---------------- RMSNorm ----------------
__global__ __launch_bounds__(256) void rmsnorm_kernel(const float* __restrict__ x,
                                                      const float* __restrict__ w,
                                                      float* __restrict__ out)
{
    int row = blockIdx.x;
    const float* xr = x + (size_t)row * DMODEL;
    float ss = 0.f;
    for (int d = threadIdx.x; d < DMODEL; d += 256) { float v = xr[d]; ss += v * v; }
    __shared__ float red[8];
    #pragma unroll
    for (int off = 16; off; off >>= 1) ss += __shfl_xor_sync(0xffffffffu, ss, off);
    if ((threadIdx.x & 31) == 0) red[threadIdx.x >> 5] = ss;
    __syncthreads();
    __shared__ float sinv;
    if (threadIdx.x == 0) {
        float tot = 0.f;
        #pragma unroll
        for (int i = 0; i < 8; i++) tot += red[i];
        sinv = 1.f / sqrtf(tot / (float)DMODEL + EPSV);
    }
    __syncthreads();
    float si = sinv;
    for (int d = threadIdx.x; d < DMODEL; d += 256)
        out[(size_t)row * DMODEL + d] = xr[d] * si * w[d];
}

// ---------------- per-(token,head) RMSNorm + RoPE ----------------
__global__ __launch_bounds__(128) void qknorm_rope_kernel(float* __restrict__ buf,
                                                          const float* __restrict__ w,
                                                          int nh)
{
    int row = blockIdx.x;
    int pos = row / nh;
    float* p = buf + (size_t)row * HDIM;
    int tid = threadIdx.x;
    float v = p[tid];
    float ss = v * v;
    #pragma unroll
    for (int off = 16; off; off >>= 1) ss += __shfl_xor_sync(0xffffffffu, ss, off);
    __shared__ float red[4];
    if ((tid & 31) == 0) red[tid >> 5] = ss;
    __syncthreads();
    __shared__ float sinv;
    if (tid == 0) sinv = 1.f / sqrtf((red[0] + red[1] + red[2] + red[3]) / (float)HDIM + EPSV);
    __shared__ float shn[HDIM];
    __syncthreads();
    shn[tid] = v * sinv * w[tid];
    __syncthreads();
    if (tid < 64) {
        float x1 = shn[tid], x2 = shn[tid + 64];
        float c = g_cos[pos * 64 + tid], s = g_sin[pos * 64 + tid];
        p[tid]      = x1 * c - x2 * s;
        p[tid + 64] = x2 * c + x1 * s;
    }
}

// ---------------- flash attention (fp32, causal, GQA) ----------------
__global__ __launch_bounds__(128) void attn_kernel()
{
    __shared__ __align__(16) float Qs[32][HDIM];
    __shared__ __align__(16) float Ks[32][HDIM];
    __shared__ __align__(16) float Vs[32][HDIM];
    int h = blockIdx.y;
    int q0 = blockIdx.x * 32;
    int kvh = h >> 2;
    int tid = threadIdx.x;
    int r = tid >> 2, qd = tid & 3;

    for (int i = tid; i < 32 * HDIM; i += 128) {
        int row = i >> 7, d = i & 127;
        Qs[row][d] = g_q[(size_t)(q0 + row) * (NH * HDIM) + h * HDIM + d];
    }
    __syncthreads();
    float qreg[32];
    #pragma unroll
    for (int d = 0; d < 32; d++) qreg[d] = Qs[r][qd * 32 + d];

    float o[32];
    #pragma unroll
    for (int d = 0; d < 32; d++) o[d] = 0.f;
    float mrow = -INFINITY, lrow = 0.f;

    for (int k0 = 0; k0 <= q0; k0 += 32) {
        __syncthreads();
        for (int i = tid; i < 32 * HDIM; i += 128) {
            int row = i >> 7, d = i & 127;
            size_t base = (size_t)(k0 + row) * (NKVH * HDIM) + kvh * HDIM + d;
            Ks[row][d] = g_k[base];
            Vs[row][d] = g_v[base];
        }
        __syncthreads();

        float s[32];
        float tmax = -INFINITY;
        #pragma unroll
        for (int j = 0; j < 32; j++) {
            float pacc = 0.f;
            const float4* K4 = (const float4*)&Ks[j][qd * 32];
            #pragma unroll
            for (int d4 = 0; d4 < 8; d4++) {
                float4 kk = K4[d4];
                pacc += qreg[d4*4+0]*kk.x + qreg[d4*4+1]*kk.y
                      + qreg[d4*4+2]*kk.z + qreg[d4*4+3]*kk.w;
            }
            pacc += __shfl_xor_sync(0xffffffffu, pacc, 1);
            pacc += __shfl_xor_sync(0xffffffffu, pacc, 2);
            pacc *= ATTN_SCALE;
            if (k0 + j > q0 + r) pacc = -INFINITY;
            s[j] = pacc;
            tmax = fmaxf(tmax, pacc);
        }
        float mnew = fmaxf(mrow, tmax);
        float alpha = __expf(mrow - mnew);
        lrow *= alpha;
        #pragma unroll
        for (int d = 0; d < 32; d++) o[d] *= alpha;
        #pragma unroll
        for (int j = 0; j < 32; j++) {
            float pv = __expf(s[j] - mnew);
            lrow += pv;
            const float4* V4 = (const float4*)&Vs[j][qd * 32];
            #pragma unroll
            for (int d4 = 0; d4 < 8; d4++) {
                float4 vv = V4[d4];
                o[d4*4+0] += pv * vv.x; o[d4*4+1] += pv * vv.y;
                o[d4*4+2] += pv * vv.z; o[d4*4+3] += pv * vv.w;
            }
        }
        mrow = mnew;
    }
    float inv = 1.f / lrow;
    size_t base = (size_t)(q0 + r) * (NH * HDIM) + h * HDIM + qd * 32;
    #pragma unroll
    for (int d = 0; d < 32; d++) g_attn[base + d] = o[d] * inv;
}

// ---------------- zero expert counters ----------------
__global__ void zero_cnt_kernel()
{
    if (threadIdx.x < NE) g_cnt[threadIdx.x] = 0;
}

// ---------------- gating / routing (fp32, exact) ----------------
__global__ __launch_bounds__(256) void gate_kernel(const float* __restrict__ gate_w,
                                                   const float* __restrict__ gate_bias)
{
    int t = blockIdx.x;
    const float* tr = g_t + (size_t)t * DMODEL;
    float acc[NE];
    #pragma unroll
    for (int e = 0; e < NE; e++) acc[e] = 0.f;
    for (int d = threadIdx.x; d < DMODEL; d += 256) {
        float xv = tr[d];
        #pragma unroll
        for (int e = 0; e < NE; e++) acc[e] += xv * gate_w[e * DMODEL + d];
    }
    __shared__ float red[NE * 8];
    int lane = threadIdx.x & 31, wid = threadIdx.x >> 5;
    #pragma unroll
    for (int e = 0; e < NE; e++) {
        float v = acc[e];
        #pragma unroll
        for (int off = 16; off; off >>= 1) v += __shfl_xor_sync(0xffffffffu, v, off);
        if (lane == 0) red[e * 8 + wid] = v;
    }
    __syncthreads();
    __shared__ float sc_s[NE];
    if (threadIdx.x < NE) {
        float sum = 0.f;
        #pragma unroll
        for (int wq = 0; wq < 8; wq++) sum += red[threadIdx.x * 8 + wq];
        sc_s[threadIdx.x] = 1.f / (1.f + expf(-sum));
    }
    __syncthreads();
    if (threadIdx.x == 0) {
        float sc[NE], s2[NE];
        #pragma unroll
        for (int e = 0; e < NE; e++) { sc[e] = sc_s[e]; s2[e] = sc[e] + gate_bias[e]; }
        float gs[NG];
        #pragma unroll
        for (int gq = 0; gq < NG; gq++) {
            float m1 = -INFINITY, m2 = -INFINITY;
            #pragma unroll
            for (int j = 0; j < NE / NG; j++) {
                float vv = s2[gq * (NE / NG) + j];
                if (vv > m1) { m2 = m1; m1 = vv; }
                else if (vv > m2) { m2 = vv; }
            }
            gs[gq] = m1 + m2;
        }
        bool gsel[NG] = {false, false, false, false};
        {
            float gtmp[NG];
            #pragma unroll
            for (int gq = 0; gq < NG; gq++) gtmp[gq] = gs[gq];
            for (int it = 0; it < NTKG; it++) {
                int bi = 0; float bv = -INFINITY;
                #pragma unroll
                for (int gq = 0; gq < NG; gq++)
                    if (gtmp[gq] > bv) { bv = gtmp[gq]; bi = gq; }
                gsel[bi] = true; gtmp[bi] = -INFINITY;
            }
        }
        float masked[NE];
        #pragma unroll
        for (int e = 0; e < NE; e++) masked[e] = gsel[e >> 2] ? s2[e] : 0.f;
        int inds[NTOPK];
        for (int it = 0; it < NTOPK; it++) {
            int bi = 0; float bv = -INFINITY;
            #pragma unroll
            for (int e = 0; e < NE; e++)
                if (masked[e] > bv) { bv = masked[e]; bi = e; }
            inds[it] = bi; masked[bi] = -INFINITY;
        }
        float wv[NTOPK], wsum = 0.f;
        #pragma unroll
        for (int i = 0; i < NTOPK; i++) { wv[i] = sc[inds[i]]; wsum += wv[i]; }
        float invw = RSF / (wsum + 1e-20f);
        float crow[NE];
        #pragma unroll
        for (int e = 0; e < NE; e++) crow[e] = 0.f;
        #pragma unroll
        for (int i = 0; i < NTOPK; i++) crow[inds[i]] += wv[i] * invw;
        #pragma unroll
        for (int e = 0; e < NE; e++) g_Cw[t * NE + e] = crow[e];
        #pragma unroll
        for (int i = 0; i < NTOPK; i++) {
            int e = inds[i];
            int posn = atomicAdd(&g_cnt[e], 1);
            g_bucket[e * NT + posn] = t;
        }
    }
}

// ---------------- elementwise combines ----------------
__global__ __launch_bounds__(256) void combine_expert_kernel()
{
    int e = blockIdx.y;
    int cnt = g_cnt[e];
    size_t idx = (size_t)blockIdx.x * 256 + threadIdx.x;
    int m = (int)(idx / EI);
    if (m >= cnt) return;
    int tok = g_bucket[e * NT + m];
    float w = g_Cw[tok * NE + e];
    size_t o = ((size_t)e * NT + m) * EI + (idx % EI);
    float gv = g_eg[o], uv = g_eu[o];
    g_eg[o] = (gv / (1.f + expf(-gv))) * uv * w;
}

__global__ __launch_bounds__(256) void combine_shared_kernel()
{
    size_t idx = (size_t)blockIdx.x * 256 + threadIdx.x;
    if (idx >= (size_t)NT * SHI) return;
    float gv = g_sg[idx], uv = g_su[idx];
    g_sg[idx] = (gv / (1.f + expf(-gv))) * uv;
}

// ---------------- final: out = h1 + y ----------------
__global__ void final_add_kernel(float* __restrict__ out)
{
    int i = blockIdx.x * blockDim.x + threadIdx.x;
    if (i < NT * DMODEL) out[i] = g_h1[i] + g_y[i];
}

// ---------------- launch ----------------
extern "C" void kernel_launch(void* const* d_in, const int* in_sizes, int n_in,
                              void* d_out, int out_size)
{
    const float* x        = (const float*)d_in[0];
    const float* w_q      = (const float*)d_in[1];
    const float* w_k      = (const float*)d_in[2];
    const float* w_v      = (const float*)d_in[3];
    const float* w_o      = (const float*)d_in[4];
    const float* q_norm_w = (const float*)d_in[5];
    const float* k_norm_w = (const float*)d_in[6];
    const float* ln1_w    = (const float*)d_in[7];
    const float* ln2_w    = (const float*)d_in[8];
    const float* gate_w   = (const float*)d_in[9];
    const float* gate_b   = (const float*)d_in[10];
    const float* wg       = (const float*)d_in[11];
    const float* wu       = (const float*)d_in[12];
    const float* wd       = (const float*)d_in[13];
    const float* sh_g     = (const float*)d_in[14];
    const float* sh_u     = (const float*)d_in[15];
    const float* sh_d     = (const float*)d_in[16];
    float* out = (float*)d_out;

    static int attr_done = 0;
    if (!attr_done) {
        cudaFuncSetAttribute(qkv3_kernel,  cudaFuncAttributeMaxDynamicSharedMemorySize, GEMM_SMEM);
        cudaFuncSetAttribute(gemm3o_kernel,cudaFuncAttributeMaxDynamicSharedMemorySize, GEMM_SMEM);
        cudaFuncSetAttribute(dense1_kernel,cudaFuncAttributeMaxDynamicSharedMemorySize, GEMM_SMEM);
        cudaFuncSetAttribute(egu1_kernel,  cudaFuncAttributeMaxDynamicSharedMemorySize, GEMM_SMEM);
        cudaFuncSetAttribute(edown1_kernel,cudaFuncAttributeMaxDynamicSharedMemorySize, GEMM_SMEM);
        attr_done = 1;
    }

    float *ph, *pq, *pk, *pattn, *ph1, *pt, *peg, *peu, *psg, *psu, *py;
    cudaGetSymbolAddress((void**)&ph,    g_h);
    cudaGetSymbolAddress((void**)&pq,    g_q);
    cudaGetSymbolAddress((void**)&pk,    g_k);
    cudaGetSymbolAddress((void**)&pattn, g_attn);
    cudaGetSymbolAddress((void**)&ph1,   g_h1);
    cudaGetSymbolAddress((void**)&pt,    g_t);
    cudaGetSymbolAddress((void**)&peg,   g_eg);
    cudaGetSymbolAddress((void**)&peu,   g_eu);
    cudaGetSymbolAddress((void**)&psg,   g_sg);
    cudaGetSymbolAddress((void**)&psu,   g_su);
    cudaGetSymbolAddress((void**)&py,    g_y);

    // 0. RoPE table
    rope_table_kernel<<<LSEQ, 64>>>();
    // 1. pre-attn norm
    rmsnorm_kernel<<<LSEQ, 256>>>(x, ln1_w, ph);
    // 2. fused QKV projection (3xTF32, pipelined)
    qkv3_kernel<<<dim3(24, 16), 256, GEMM_SMEM>>>(ph, w_q, w_k, w_v);
    // 3. q/k rmsnorm + rope
    qknorm_rope_kernel<<<LSEQ * NH, 128>>>(pq, q_norm_w, NH);
    qknorm_rope_kernel<<<LSEQ * NKVH, 128>>>(pk, k_norm_w, NKVH);
    // 4. attention (fp32)
    attn_kernel<<<dim3(LSEQ / 32, NH), 128>>>();
    // 5. output proj + residual (3xTF32)
    gemm3o_kernel<<<dim3(16, 16), 256, GEMM_SMEM>>>(pattn, w_o, ph1, x);
    // 6. post-attn norm
    rmsnorm_kernel<<<LSEQ, 256>>>(ph1, ln2_w, pt);
    // 7. routing (fp32, exact)
    zero_cnt_kernel<<<1, 32>>>();
    gate_kernel<<<NT, 256>>>(gate_w, gate_b);
    // 8. shared expert (1xTF32): gate, up, combine, down (down STORES y)
    dense1_kernel<<<dim3(16, 16), 256, GEMM_SMEM>>>(pt, sh_g, psg, SHI, DMODEL);
    dense1_kernel<<<dim3(16, 16), 256, GEMM_SMEM>>>(pt, sh_u, psu, SHI, DMODEL);
    combine_shared_kernel<<<(int)(((size_t)NT * SHI + 255) / 256), 256>>>();
    dense1_kernel<<<dim3(16, 16), 256, GEMM_SMEM>>>(psg, sh_d, py, DMODEL, SHI);
    // 9. routed experts (1xTF32, gathered)
    egu1_kernel<<<dim3(EI / 128, NT / 128, NE), 256, GEMM_SMEM>>>(wg, peg);
    egu1_kernel<<<dim3(EI / 128, NT / 128, NE), 256, GEMM_SMEM>>>(wu, peu);
    combine_expert_kernel<<<dim3((int)(((size_t)NT * EI + 255) / 256), NE), 256>>>();
    edown1_kernel<<<dim3(DMODEL / 128, NT / 128, NE), 256, GEMM_SMEM>>>(wd);
    // 10. final residual add
    final_add_kernel<<<(NT * DMODEL + 255) / 256, 256>>>(out);
    (void)in_sizes; (void)n_in; (void)out_size;
}

// round 9
// speedup vs baseline: 1.2365x; 1.0240x over previous
#include <cuda_runtime.h>
#include <math.h>

#define LSEQ 2048
#define DMODEL 2048
#define NH 16
#define NKVH 4
#define HDIM 128
#define NE 16
#define NTOPK 4
#define NG 4
#define NTKG 2
#define EI 1024
#define SHI 2048
#define NT 2048
#define EPSV 1e-5f
#define ATTN_SCALE 0.08838834764831845f
#define RSF 2.5f

// smem tile geometry: 128 rows x 32 k-floats, stride 36 (conflict-free: bank=(4r+c)&31)
#define TSTRIDE 36
#define TSTAGE  (128*TSTRIDE)          // floats per stage per matrix
#define GEMM_SMEM (4*TSTAGE*4)         // bytes: 2 stages x (A+B) = 73728

// ---------------- scratch ----------------
__device__ float g_h   [LSEQ*DMODEL];
__device__ float g_q   [LSEQ*NH*HDIM];
__device__ float g_k   [LSEQ*NKVH*HDIM];
__device__ float g_v   [LSEQ*NKVH*HDIM];
__device__ float g_attn[LSEQ*NH*HDIM];
__device__ float g_h1  [LSEQ*DMODEL];
__device__ float g_t   [LSEQ*DMODEL];
__device__ float g_Cw  [NT*NE];
__device__ int   g_cnt [NE];
__device__ int   g_bucket[NE*NT];
__device__ float g_eg  [(size_t)NE*NT*EI];
__device__ float g_eu  [(size_t)NE*NT*EI];
__device__ float g_sg  [(size_t)NT*SHI];
__device__ float g_su  [(size_t)NT*SHI];
__device__ float g_y   [(size_t)NT*DMODEL];
__device__ float g_cos [LSEQ*64];
__device__ float g_sin [LSEQ*64];

// ---------------- helpers ----------------
__device__ __forceinline__ unsigned f2tf(float f){
    unsigned u; asm("cvt.rna.tf32.f32 %0,%1;" : "=r"(u) : "f"(f)); return u;
}
__device__ __forceinline__ void mma_tf32(float c[4],
    unsigned a0, unsigned a1, unsigned a2, unsigned a3, unsigned b0, unsigned b1)
{
    asm volatile("mma.sync.aligned.m16n8k8.row.col.f32.tf32.tf32.f32 "
        "{%0,%1,%2,%3},{%4,%5,%6,%7},{%8,%9},{%0,%1,%2,%3};"
        : "+f"(c[0]), "+f"(c[1]), "+f"(c[2]), "+f"(c[3])
        : "r"(a0), "r"(a1), "r"(a2), "r"(a3), "r"(b0), "r"(b1));
}
__device__ __forceinline__ unsigned sptr(const void* p){
    return (unsigned)__cvta_generic_to_shared(p);
}
#define CPA16(dst, src, n) asm volatile( \
    "cp.async.cg.shared.global [%0], [%1], 16, %2;\n" :: "r"(dst), "l"(src), "r"(n))
#define CPCOMMIT() asm volatile("cp.async.commit_group;\n" ::: "memory")
#define CPWAIT0()  asm volatile("cp.async.wait_group 0;\n" ::: "memory")

// ---------------- MMA stage compute (reads raw fp32 smem, converts at use) ----------------
__device__ __forceinline__ void mma_stage_1x(const float* As, const float* Bs,
    float (*acc)[4][4], int wm, int wn, int r, int c)
{
    #pragma unroll
    for (int ks = 0; ks < 32; ks += 8) {
        unsigned aF[4][4], bF[4][2];
        #pragma unroll
        for (int mt = 0; mt < 4; mt++) {
            const float* p = As + (wm + mt*16 + r)*TSTRIDE + ks + c;
            aF[mt][0] = f2tf(p[0]);          aF[mt][1] = f2tf(p[8*TSTRIDE]);
            aF[mt][2] = f2tf(p[4]);          aF[mt][3] = f2tf(p[8*TSTRIDE+4]);
        }
        #pragma unroll
        for (int nt = 0; nt < 4; nt++) {
            const float* p = Bs + (wn + nt*8 + r)*TSTRIDE + ks + c;
            bF[nt][0] = f2tf(p[0]);          bF[nt][1] = f2tf(p[4]);
        }
        #pragma unroll
        for (int mt = 0; mt < 4; mt++)
            #pragma unroll
            for (int nt = 0; nt < 4; nt++)
                mma_tf32(acc[mt][nt], aF[mt][0],aF[mt][1],aF[mt][2],aF[mt][3],
                         bF[nt][0],bF[nt][1]);
    }
}

__device__ __forceinline__ void mma_stage_3x(const float* As, const float* Bs,
    float (*acc)[4][4], int wm, int wn, int r, int c)
{
    #pragma unroll
    for (int ks = 0; ks < 32; ks += 8) {
        unsigned aH[4][4], aL[4][4], bH[4][2], bL[4][2];
        #pragma unroll
        for (int mt = 0; mt < 4; mt++) {
            const float* p = As + (wm + mt*16 + r)*TSTRIDE + ks + c;
            float v0 = p[0], v1 = p[8*TSTRIDE], v2 = p[4], v3 = p[8*TSTRIDE+4];
            aH[mt][0]=f2tf(v0); aL[mt][0]=f2tf(v0-__uint_as_float(aH[mt][0]));
            aH[mt][1]=f2tf(v1); aL[mt][1]=f2tf(v1-__uint_as_float(aH[mt][1]));
            aH[mt][2]=f2tf(v2); aL[mt][2]=f2tf(v2-__uint_as_float(aH[mt][2]));
            aH[mt][3]=f2tf(v3); aL[mt][3]=f2tf(v3-__uint_as_float(aH[mt][3]));
        }
        #pragma unroll
        for (int nt = 0; nt < 4; nt++) {
            const float* p = Bs + (wn + nt*8 + r)*TSTRIDE + ks + c;
            float v0 = p[0], v1 = p[4];
            bH[nt][0]=f2tf(v0); bL[nt][0]=f2tf(v0-__uint_as_float(bH[nt][0]));
            bH[nt][1]=f2tf(v1); bL[nt][1]=f2tf(v1-__uint_as_float(bH[nt][1]));
        }
        #pragma unroll
        for (int mt = 0; mt < 4; mt++)
            #pragma unroll
            for (int nt = 0; nt < 4; nt++) {
                mma_tf32(acc[mt][nt], aH[mt][0],aH[mt][1],aH[mt][2],aH[mt][3], bH[nt][0],bH[nt][1]);
                mma_tf32(acc[mt][nt], aL[mt][0],aL[mt][1],aL[mt][2],aL[mt][3], bH[nt][0],bH[nt][1]);
                mma_tf32(acc[mt][nt], aH[mt][0],aH[mt][1],aH[mt][2],aH[mt][3], bL[nt][0],bL[nt][1]);
            }
    }
}

// ============ fused QKV projection (3xTF32, pipelined) ============
__global__ __launch_bounds__(256, 2) void qkv3_kernel(const float* __restrict__ A,
    const float* __restrict__ wq, const float* __restrict__ wk, const float* __restrict__ wv)
{
    extern __shared__ float sm[];
    float* As = sm;
    float* Bs = sm + 2*TSTAGE;
    const int K = DMODEL;
    int tid = threadIdx.x, lane = tid & 31, warp = tid >> 5;
    int m0 = blockIdx.y * 128, n0 = blockIdx.x * 128;
    int wm = (warp & 1) * 64, wn = (warp >> 1) * 32;
    int r = lane >> 2, c = lane & 3;

    const float* B; float* Cp; int ldc, ncol0;
    if (n0 < 2048)      { B = wq + (size_t)n0 * K;          Cp = g_q; ldc = NH*HDIM;   ncol0 = n0; }
    else if (n0 < 2560) { B = wk + (size_t)(n0 - 2048) * K; Cp = g_k; ldc = NKVH*HDIM; ncol0 = n0 - 2048; }
    else                { B = wv + (size_t)(n0 - 2560) * K; Cp = g_v; ldc = NKVH*HDIM; ncol0 = n0 - 2560; }

    const float* aSrc[4]; const float* bSrc[4]; int soff[4];
    #pragma unroll
    for (int i = 0; i < 4; i++) {
        int idx = tid + i * 256, row = idx >> 3, ch = idx & 7;
        soff[i] = row * TSTRIDE + ch * 4;
        aSrc[i] = A + (size_t)(m0 + row) * K + ch * 4;
        bSrc[i] = B + (size_t)row * K + ch * 4;
    }
    #pragma unroll
    for (int i = 0; i < 4; i++) {
        CPA16(sptr(As + soff[i]), aSrc[i], 16);
        CPA16(sptr(Bs + soff[i]), bSrc[i], 16);
    }
    CPCOMMIT();

    float acc[4][4][4] = {};
    for (int k0 = 0; k0 < K; k0 += 32) {
        CPWAIT0(); __syncthreads();
        int cur = (k0 >> 5) & 1, nxt = cur ^ 1;
        if (k0 + 32 < K) {
            #pragma unroll
            for (int i = 0; i < 4; i++) {
                CPA16(sptr(As + nxt*TSTAGE + soff[i]), aSrc[i] + k0 + 32, 16);
                CPA16(sptr(Bs + nxt*TSTAGE + soff[i]), bSrc[i] + k0 + 32, 16);
            }
            CPCOMMIT();
        }
        mma_stage_3x(As + cur*TSTAGE, Bs + cur*TSTAGE, acc, wm, wn, r, c);
    }
    int c2 = (lane & 3) * 2;
    #pragma unroll
    for (int mt = 0; mt < 4; mt++) {
        int mrow = m0 + wm + mt * 16 + r;
        #pragma unroll
        for (int nt = 0; nt < 4; nt++) {
            int col = ncol0 + wn + nt * 8 + c2;
            size_t i00 = (size_t)mrow * ldc + col;
            size_t i10 = (size_t)(mrow + 8) * ldc + col;
            Cp[i00] = acc[mt][nt][0]; Cp[i00+1] = acc[mt][nt][1];
            Cp[i10] = acc[mt][nt][2]; Cp[i10+1] = acc[mt][nt][3];
        }
    }
}

// ============ o-proj + residual (3xTF32, pipelined) ============
__global__ __launch_bounds__(256, 2) void gemm3o_kernel(const float* __restrict__ A,
    const float* __restrict__ B, float* __restrict__ C, const float* __restrict__ R)
{
    extern __shared__ float sm[];
    float* As = sm;
    float* Bs = sm + 2*TSTAGE;
    const int K = NH*HDIM, N = DMODEL;
    int tid = threadIdx.x, lane = tid & 31, warp = tid >> 5;
    int m0 = blockIdx.y * 128, n0 = blockIdx.x * 128;
    int wm = (warp & 1) * 64, wn = (warp >> 1) * 32;
    int r = lane >> 2, c = lane & 3;

    const float* aSrc[4]; const float* bSrc[4]; int soff[4];
    #pragma unroll
    for (int i = 0; i < 4; i++) {
        int idx = tid + i * 256, row = idx >> 3, ch = idx & 7;
        soff[i] = row * TSTRIDE + ch * 4;
        aSrc[i] = A + (size_t)(m0 + row) * K + ch * 4;
        bSrc[i] = B + (size_t)(n0 + row) * K + ch * 4;
    }
    #pragma unroll
    for (int i = 0; i < 4; i++) {
        CPA16(sptr(As + soff[i]), aSrc[i], 16);
        CPA16(sptr(Bs + soff[i]), bSrc[i], 16);
    }
    CPCOMMIT();

    float acc[4][4][4] = {};
    for (int k0 = 0; k0 < K; k0 += 32) {
        CPWAIT0(); __syncthreads();
        int cur = (k0 >> 5) & 1, nxt = cur ^ 1;
        if (k0 + 32 < K) {
            #pragma unroll
            for (int i = 0; i < 4; i++) {
                CPA16(sptr(As + nxt*TSTAGE + soff[i]), aSrc[i] + k0 + 32, 16);
                CPA16(sptr(Bs + nxt*TSTAGE + soff[i]), bSrc[i] + k0 + 32, 16);
            }
            CPCOMMIT();
        }
        mma_stage_3x(As + cur*TSTAGE, Bs + cur*TSTAGE, acc, wm, wn, r, c);
    }
    int c2 = (lane & 3) * 2;
    #pragma unroll
    for (int mt = 0; mt < 4; mt++) {
        int mrow = m0 + wm + mt * 16 + r;
        #pragma unroll
        for (int nt = 0; nt < 4; nt++) {
            int col = n0 + wn + nt * 8 + c2;
            size_t i00 = (size_t)mrow * N + col;
            size_t i10 = (size_t)(mrow + 8) * N + col;
            C[i00] = acc[mt][nt][0] + R[i00]; C[i00+1] = acc[mt][nt][1] + R[i00+1];
            C[i10] = acc[mt][nt][2] + R[i10]; C[i10+1] = acc[mt][nt][3] + R[i10+1];
        }
    }
}

// ============ dual dense 1xTF32 GEMM (z selects gate/up): C[M,N] = A@B^T ============
__global__ __launch_bounds__(256, 2) void dense1_dual_kernel(const float* __restrict__ A,
    const float* __restrict__ B0, const float* __restrict__ B1,
    float* __restrict__ C0, float* __restrict__ C1, int N, int K)
{
    const float* Bsel = blockIdx.z ? B1 : B0;
    float* Csel = blockIdx.z ? C1 : C0;
    extern __shared__ float sm[];
    float* As = sm;
    float* Bs = sm + 2*TSTAGE;
    int tid = threadIdx.x, lane = tid & 31, warp = tid >> 5;
    int m0 = blockIdx.y * 128, n0 = blockIdx.x * 128;
    int wm = (warp & 1) * 64, wn = (warp >> 1) * 32;
    int r = lane >> 2, c = lane & 3;

    const float* aSrc[4]; const float* bSrc[4]; int soff[4];
    #pragma unroll
    for (int i = 0; i < 4; i++) {
        int idx = tid + i * 256, row = idx >> 3, ch = idx & 7;
        soff[i] = row * TSTRIDE + ch * 4;
        aSrc[i] = A + (size_t)(m0 + row) * K + ch * 4;
        bSrc[i] = Bsel + (size_t)(n0 + row) * K + ch * 4;
    }
    #pragma unroll
    for (int i = 0; i < 4; i++) {
        CPA16(sptr(As + soff[i]), aSrc[i], 16);
        CPA16(sptr(Bs + soff[i]), bSrc[i], 16);
    }
    CPCOMMIT();

    float acc[4][4][4] = {};
    for (int k0 = 0; k0 < K; k0 += 32) {
        CPWAIT0(); __syncthreads();
        int cur = (k0 >> 5) & 1, nxt = cur ^ 1;
        if (k0 + 32 < K) {
            #pragma unroll
            for (int i = 0; i < 4; i++) {
                CPA16(sptr(As + nxt*TSTAGE + soff[i]), aSrc[i] + k0 + 32, 16);
                CPA16(sptr(Bs + nxt*TSTAGE + soff[i]), bSrc[i] + k0 + 32, 16);
            }
            CPCOMMIT();
        }
        mma_stage_1x(As + cur*TSTAGE, Bs + cur*TSTAGE, acc, wm, wn, r, c);
    }
    int c2 = (lane & 3) * 2;
    #pragma unroll
    for (int mt = 0; mt < 4; mt++) {
        int mrow = m0 + wm + mt * 16 + r;
        #pragma unroll
        for (int nt = 0; nt < 4; nt++) {
            int col = n0 + wn + nt * 8 + c2;
            size_t i00 = (size_t)mrow * N + col;
            size_t i10 = (size_t)(mrow + 8) * N + col;
            Csel[i00] = acc[mt][nt][0]; Csel[i00+1] = acc[mt][nt][1];
            Csel[i10] = acc[mt][nt][2]; Csel[i10+1] = acc[mt][nt][3];
        }
    }
}

// ============ dense 1xTF32 GEMM (pipelined): C[M,N] = A[M,K]@B[N,K]^T ============
__global__ __launch_bounds__(256, 2) void dense1_kernel(const float* __restrict__ A,
    const float* __restrict__ B, float* __restrict__ C, int N, int K)
{
    extern __shared__ float sm[];
    float* As = sm;
    float* Bs = sm + 2*TSTAGE;
    int tid = threadIdx.x, lane = tid & 31, warp = tid >> 5;
    int m0 = blockIdx.y * 128, n0 = blockIdx.x * 128;
    int wm = (warp & 1) * 64, wn = (warp >> 1) * 32;
    int r = lane >> 2, c = lane & 3;

    const float* aSrc[4]; const float* bSrc[4]; int soff[4];
    #pragma unroll
    for (int i = 0; i < 4; i++) {
        int idx = tid + i * 256, row = idx >> 3, ch = idx & 7;
        soff[i] = row * TSTRIDE + ch * 4;
        aSrc[i] = A + (size_t)(m0 + row) * K + ch * 4;
        bSrc[i] = B + (size_t)(n0 + row) * K + ch * 4;
    }
    #pragma unroll
    for (int i = 0; i < 4; i++) {
        CPA16(sptr(As + soff[i]), aSrc[i], 16);
        CPA16(sptr(Bs + soff[i]), bSrc[i], 16);
    }
    CPCOMMIT();

    float acc[4][4][4] = {};
    for (int k0 = 0; k0 < K; k0 += 32) {
        CPWAIT0(); __syncthreads();
        int cur = (k0 >> 5) & 1, nxt = cur ^ 1;
        if (k0 + 32 < K) {
            #pragma unroll
            for (int i = 0; i < 4; i++) {
                CPA16(sptr(As + nxt*TSTAGE + soff[i]), aSrc[i] + k0 + 32, 16);
                CPA16(sptr(Bs + nxt*TSTAGE + soff[i]), bSrc[i] + k0 + 32, 16);
            }
            CPCOMMIT();
        }
        mma_stage_1x(As + cur*TSTAGE, Bs + cur*TSTAGE, acc, wm, wn, r, c);
    }
    int c2 = (lane & 3) * 2;
    #pragma unroll
    for (int mt = 0; mt < 4; mt++) {
        int mrow = m0 + wm + mt * 16 + r;
        #pragma unroll
        for (int nt = 0; nt < 4; nt++) {
            int col = n0 + wn + nt * 8 + c2;
            size_t i00 = (size_t)mrow * N + col;
            size_t i10 = (size_t)(mrow + 8) * N + col;
            C[i00] = acc[mt][nt][0]; C[i00+1] = acc[mt][nt][1];
            C[i10] = acc[mt][nt][2]; C[i10+1] = acc[mt][nt][3];
        }
    }
}

// ============ gathered expert gate+up GEMM (1xTF32), z = e*2 + which ============
__global__ __launch_bounds__(256, 2) void egu1_kernel(const float* __restrict__ wg,
    const float* __restrict__ wu)
{
    int e = blockIdx.z >> 1;
    int which = blockIdx.z & 1;
    int cnt = g_cnt[e];
    int m0 = blockIdx.y * 128;
    if (m0 >= cnt) return;
    int n0 = blockIdx.x * 128;
    const float* W = which ? wu : wg;
    float* Cout = which ? g_eu : g_eg;
    extern __shared__ float sm[];
    float* As = sm;
    float* Bs = sm + 2*TSTAGE;
    __shared__ int toks[128];
    const int K = DMODEL;
    int tid = threadIdx.x, lane = tid & 31, warp = tid >> 5;
    if (tid < 128) {
        int m = m0 + tid;
        toks[tid] = (m < cnt) ? g_bucket[e * NT + m] : -1;
    }
    __syncthreads();
    const float* B = W + (size_t)e * EI * DMODEL + (size_t)n0 * K;
    int wm = (warp & 1) * 64, wn = (warp >> 1) * 32;
    int r = lane >> 2, c = lane & 3;

    const float* aSrc[4]; const float* bSrc[4]; int soff[4]; int aBytes[4];
    #pragma unroll
    for (int i = 0; i < 4; i++) {
        int idx = tid + i * 256, row = idx >> 3, ch = idx & 7;
        soff[i] = row * TSTRIDE + ch * 4;
        int tok = toks[row];
        aBytes[i] = (tok >= 0) ? 16 : 0;
        aSrc[i] = g_t + (size_t)(tok >= 0 ? tok : 0) * K + ch * 4;
        bSrc[i] = B + (size_t)row * K + ch * 4;
    }
    #pragma unroll
    for (int i = 0; i < 4; i++) {
        CPA16(sptr(As + soff[i]), aSrc[i], aBytes[i]);
        CPA16(sptr(Bs + soff[i]), bSrc[i], 16);
    }
    CPCOMMIT();

    float acc[4][4][4] = {};
    for (int k0 = 0; k0 < K; k0 += 32) {
        CPWAIT0(); __syncthreads();
        int cur = (k0 >> 5) & 1, nxt = cur ^ 1;
        if (k0 + 32 < K) {
            #pragma unroll
            for (int i = 0; i < 4; i++) {
                CPA16(sptr(As + nxt*TSTAGE + soff[i]), aSrc[i] + k0 + 32, aBytes[i]);
                CPA16(sptr(Bs + nxt*TSTAGE + soff[i]), bSrc[i] + k0 + 32, 16);
            }
            CPCOMMIT();
        }
        mma_stage_1x(As + cur*TSTAGE, Bs + cur*TSTAGE, acc, wm, wn, r, c);
    }
    int c2 = (lane & 3) * 2;
    #pragma unroll
    for (int mt = 0; mt < 4; mt++) {
        int mloc = wm + mt * 16 + r;
        int m = m0 + mloc;
        #pragma unroll
        for (int nt = 0; nt < 4; nt++) {
            int col = n0 + wn + nt * 8 + c2;
            if (m < cnt) {
                size_t i00 = ((size_t)e * NT + m) * EI + col;
                Cout[i00] = acc[mt][nt][0]; Cout[i00+1] = acc[mt][nt][1];
            }
            if (m + 8 < cnt) {
                size_t i10 = ((size_t)e * NT + m + 8) * EI + col;
                Cout[i10] = acc[mt][nt][2]; Cout[i10+1] = acc[mt][nt][3];
            }
        }
    }
}

// ============ expert down GEMM (1xTF32, pipelined) + scatter atomicAdd ============
__global__ __launch_bounds__(256, 2) void edown1_kernel(const float* __restrict__ wd)
{
    int e = blockIdx.z;
    int cnt = g_cnt[e];
    int m0 = blockIdx.y * 128;
    if (m0 >= cnt) return;
    int n0 = blockIdx.x * 128;
    extern __shared__ float sm[];
    float* As = sm;
    float* Bs = sm + 2*TSTAGE;
    __shared__ int toks[128];
    const int K = EI;
    int tid = threadIdx.x, lane = tid & 31, warp = tid >> 5;
    if (tid < 128) {
        int m = m0 + tid;
        toks[tid] = (m < cnt) ? g_bucket[e * NT + m] : -1;
    }
    __syncthreads();
    const float* Ae = g_eg + ((size_t)e * NT + m0) * EI;
    const float* B = wd + (size_t)e * DMODEL * EI + (size_t)n0 * K;
    int wm = (warp & 1) * 64, wn = (warp >> 1) * 32;
    int r = lane >> 2, c = lane & 3;

    const float* aSrc[4]; const float* bSrc[4]; int soff[4]; int aBytes[4];
    #pragma unroll
    for (int i = 0; i < 4; i++) {
        int idx = tid + i * 256, row = idx >> 3, ch = idx & 7;
        soff[i] = row * TSTRIDE + ch * 4;
        bool ok = (m0 + row) < cnt;
        aBytes[i] = ok ? 16 : 0;
        aSrc[i] = Ae + (size_t)(ok ? row : 0) * K + ch * 4;
        bSrc[i] = B + (size_t)row * K + ch * 4;
    }
    #pragma unroll
    for (int i = 0; i < 4; i++) {
        CPA16(sptr(As + soff[i]), aSrc[i], aBytes[i]);
        CPA16(sptr(Bs + soff[i]), bSrc[i], 16);
    }
    CPCOMMIT();

    float acc[4][4][4] = {};
    for (int k0 = 0; k0 < K; k0 += 32) {
        CPWAIT0(); __syncthreads();
        int cur = (k0 >> 5) & 1, nxt = cur ^ 1;
        if (k0 + 32 < K) {
            #pragma unroll
            for (int i = 0; i < 4; i++) {
                CPA16(sptr(As + nxt*TSTAGE + soff[i]), aSrc[i] + k0 + 32, aBytes[i]);
                CPA16(sptr(Bs + nxt*TSTAGE + soff[i]), bSrc[i] + k0 + 32, 16);
            }
            CPCOMMIT();
        }
        mma_stage_1x(As + cur*TSTAGE, Bs + cur*TSTAGE, acc, wm, wn, r, c);
    }
    int c2 = (lane & 3) * 2;
    #pragma unroll
    for (int mt = 0; mt < 4; mt++) {
        int mloc = wm + mt * 16 + r;
        #pragma unroll
        for (int nt = 0; nt < 4; nt++) {
            int col = n0 + wn + nt * 8 + c2;
            if (m0 + mloc < cnt) {
                int tok = toks[mloc];
                atomicAdd(&g_y[(size_t)tok * DMODEL + col],     acc[mt][nt][0]);
                atomicAdd(&g_y[(size_t)tok * DMODEL + col + 1], acc[mt][nt][1]);
            }
            if (m0 + mloc + 8 < cnt) {
                int tok = toks[mloc + 8];
                atomicAdd(&g_y[(size_t)tok * DMODEL + col],     acc[mt][nt][2]);
                atomicAdd(&g_y[(size_t)tok * DMODEL + col + 1], acc[mt][nt][3]);
            }
        }
    }
}

// ---------------- RoPE table (double-precision trig, fast-math-immune) ----------------
__global__ void rope_table_kernel()
{
    int pos = blockIdx.x, j = threadIdx.x;
    float p    = (float)pow(1000000.0, (double)j / 64.0);
    float freq = 1.0f / p;
    float ang  = (float)pos * freq;
    double sd, cd; sincos((double)ang, &sd, &cd);
    g_cos[pos * 64 + j] = (float)cd;
    g_sin[pos * 64 + j] = (float)sd;
}

// ---------------- RMSNorm ----------------
__global__ __launch_bounds__(256) void rmsnorm_kernel(const float* __restrict__ x,
                                                      const float* __restrict__ w,
                                                      float* __restrict__ out)
{
    int row = blockIdx.x;
    const float* xr = x + (size_t)row * DMODEL;
    float ss = 0.f;
    for (int d = threadIdx.x; d < DMODEL; d += 256) { float v = xr[d]; ss += v * v; }
    __shared__ float red[8];
    #pragma unroll
    for (int off = 16; off; off >>= 1) ss += __shfl_xor_sync(0xffffffffu, ss, off);
    if ((threadIdx.x & 31) == 0) red[threadIdx.x >> 5] = ss;
    __syncthreads();
    __shared__ float sinv;
    if (threadIdx.x == 0) {
        float tot = 0.f;
        #pragma unroll
        for (int i = 0; i < 8; i++) tot += red[i];
        sinv = 1.f / sqrtf(tot / (float)DMODEL + EPSV);
    }
    __syncthreads();
    float si = sinv;
    for (int d = threadIdx.x; d < DMODEL; d += 256)
        out[(size_t)row * DMODEL + d] = xr[d] * si * w[d];
}

// ---------------- per-(token,head) RMSNorm + RoPE ----------------
__global__ __launch_bounds__(128) void qknorm_rope_kernel(float* __restrict__ buf,
                                                          const float* __restrict__ w,
                                                          int nh)
{
    int row = blockIdx.x;
    int pos = row / nh;
    float* p = buf + (size_t)row * HDIM;
    int tid = threadIdx.x;
    float v = p[tid];
    float ss = v * v;
    #pragma unroll
    for (int off = 16; off; off >>= 1) ss += __shfl_xor_sync(0xffffffffu, ss, off);
    __shared__ float red[4];
    if ((tid & 31) == 0) red[tid >> 5] = ss;
    __syncthreads();
    __shared__ float sinv;
    if (tid == 0) sinv = 1.f / sqrtf((red[0] + red[1] + red[2] + red[3]) / (float)HDIM + EPSV);
    __shared__ float shn[HDIM];
    __syncthreads();
    shn[tid] = v * sinv * w[tid];
    __syncthreads();
    if (tid < 64) {
        float x1 = shn[tid], x2 = shn[tid + 64];
        float c = g_cos[pos * 64 + tid], s = g_sin[pos * 64 + tid];
        p[tid]      = x1 * c - x2 * s;
        p[tid + 64] = x2 * c + x1 * s;
    }
}

// ---------------- flash attention (fp32, causal, GQA) ----------------
__global__ __launch_bounds__(128) void attn_kernel()
{
    __shared__ __align__(16) float Qs[32][HDIM];
    __shared__ __align__(16) float Ks[32][HDIM];
    __shared__ __align__(16) float Vs[32][HDIM];
    int h = blockIdx.y;
    int q0 = blockIdx.x * 32;
    int kvh = h >> 2;
    int tid = threadIdx.x;
    int r = tid >> 2, qd = tid & 3;

    for (int i = tid; i < 32 * HDIM; i += 128) {
        int row = i >> 7, d = i & 127;
        Qs[row][d] = g_q[(size_t)(q0 + row) * (NH * HDIM) + h * HDIM + d];
    }
    __syncthreads();
    float qreg[32];
    #pragma unroll
    for (int d = 0; d < 32; d++) qreg[d] = Qs[r][qd * 32 + d];

    float o[32];
    #pragma unroll
    for (int d = 0; d < 32; d++) o[d] = 0.f;
    float mrow = -INFINITY, lrow = 0.f;

    for (int k0 = 0; k0 <= q0; k0 += 32) {
        __syncthreads();
        for (int i = tid; i < 32 * HDIM; i += 128) {
            int row = i >> 7, d = i & 127;
            size_t base = (size_t)(k0 + row) * (NKVH * HDIM) + kvh * HDIM + d;
            Ks[row][d] = g_k[base];
            Vs[row][d] = g_v[base];
        }
        __syncthreads();

        float s[32];
        float tmax = -INFINITY;
        #pragma unroll
        for (int j = 0; j < 32; j++) {
            float pacc = 0.f;
            const float4* K4 = (const float4*)&Ks[j][qd * 32];
            #pragma unroll
            for (int d4 = 0; d4 < 8; d4++) {
                float4 kk = K4[d4];
                pacc += qreg[d4*4+0]*kk.x + qreg[d4*4+1]*kk.y
                      + qreg[d4*4+2]*kk.z + qreg[d4*4+3]*kk.w;
            }
            pacc += __shfl_xor_sync(0xffffffffu, pacc, 1);
            pacc += __shfl_xor_sync(0xffffffffu, pacc, 2);
            pacc *= ATTN_SCALE;
            if (k0 + j > q0 + r) pacc = -INFINITY;
            s[j] = pacc;
            tmax = fmaxf(tmax, pacc);
        }
        float mnew = fmaxf(mrow, tmax);
        float alpha = __expf(mrow - mnew);
        lrow *= alpha;
        #pragma unroll
        for (int d = 0; d < 32; d++) o[d] *= alpha;
        #pragma unroll
        for (int j = 0; j < 32; j++) {
            float pv = __expf(s[j] - mnew);
            lrow += pv;
            const float4* V4 = (const float4*)&Vs[j][qd * 32];
            #pragma unroll
            for (int d4 = 0; d4 < 8; d4++) {
                float4 vv = V4[d4];
                o[d4*4+0] += pv * vv.x; o[d4*4+1] += pv * vv.y;
                o[d4*4+2] += pv * vv.z; o[d4*4+3] += pv * vv.w;
            }
        }
        mrow = mnew;
    }
    float inv = 1.f / lrow;
    size_t base = (size_t)(q0 + r) * (NH * HDIM) + h * HDIM + qd * 32;
    #pragma unroll
    for (int d = 0; d < 32; d++) g_attn[base + d] = o[d] * inv;
}

// ---------------- zero expert counters ----------------
__global__ void zero_cnt_kernel()
{
    if (threadIdx.x < NE) g_cnt[threadIdx.x] = 0;
}

// ---------------- gating / routing (fp32, exact) ----------------
__global__ __launch_bounds__(256) void gate_kernel(const float* __restrict__ gate_w,
                                                   const float* __restrict__ gate_bias)
{
    int t = blockIdx.x;
    const float* tr = g_t + (size_t)t * DMODEL;
    float acc[NE];
    #pragma unroll
    for (int e = 0; e < NE; e++) acc[e] = 0.f;
    for (int d = threadIdx.x; d < DMODEL; d += 256) {
        float xv = tr[d];
        #pragma unroll
        for (int e = 0; e < NE; e++) acc[e] += xv * gate_w[e * DMODEL + d];
    }
    __shared__ float red[NE * 8];
    int lane = threadIdx.x & 31, wid = threadIdx.x >> 5;
    #pragma unroll
    for (int e = 0; e < NE; e++) {
        float v = acc[e];
        #pragma unroll
        for (int off = 16; off; off >>= 1) v += __shfl_xor_sync(0xffffffffu, v, off);
        if (lane == 0) red[e * 8 + wid] = v;
    }
    __syncthreads();
    __shared__ float sc_s[NE];
    if (threadIdx.x < NE) {
        float sum = 0.f;
        #pragma unroll
        for (int wq = 0; wq < 8; wq++) sum += red[threadIdx.x * 8 + wq];
        sc_s[threadIdx.x] = 1.f / (1.f + expf(-sum));
    }
    __syncthreads();
    if (threadIdx.x == 0) {
        float sc[NE], s2[NE];
        #pragma unroll
        for (int e = 0; e < NE; e++) { sc[e] = sc_s[e]; s2[e] = sc[e] + gate_bias[e]; }
        float gs[NG];
        #pragma unroll
        for (int gq = 0; gq < NG; gq++) {
            float m1 = -INFINITY, m2 = -INFINITY;
            #pragma unroll
            for (int j = 0; j < NE / NG; j++) {
                float vv = s2[gq * (NE / NG) + j];
                if (vv > m1) { m2 = m1; m1 = vv; }
                else if (vv > m2) { m2 = vv; }
            }
            gs[gq] = m1 + m2;
        }
        bool gsel[NG] = {false, false, false, false};
        {
            float gtmp[NG];
            #pragma unroll
            for (int gq = 0; gq < NG; gq++) gtmp[gq] = gs[gq];
            for (int it = 0; it < NTKG; it++) {
                int bi = 0; float bv = -INFINITY;
                #pragma unroll
                for (int gq = 0; gq < NG; gq++)
                    if (gtmp[gq] > bv) { bv = gtmp[gq]; bi = gq; }
                gsel[bi] = true; gtmp[bi] = -INFINITY;
            }
        }
        float masked[NE];
        #pragma unroll
        for (int e = 0; e < NE; e++) masked[e] = gsel[e >> 2] ? s2[e] : 0.f;
        int inds[NTOPK];
        for (int it = 0; it < NTOPK; it++) {
            int bi = 0; float bv = -INFINITY;
            #pragma unroll
            for (int e = 0; e < NE; e++)
                if (masked[e] > bv) { bv = masked[e]; bi = e; }
            inds[it] = bi; masked[bi] = -INFINITY;
        }
        float wv[NTOPK], wsum = 0.f;
        #pragma unroll
        for (int i = 0; i < NTOPK; i++) { wv[i] = sc[inds[i]]; wsum += wv[i]; }
        float invw = RSF / (wsum + 1e-20f);
        float crow[NE];
        #pragma unroll
        for (int e = 0; e < NE; e++) crow[e] = 0.f;
        #pragma unroll
        for (int i = 0; i < NTOPK; i++) crow[inds[i]] += wv[i] * invw;
        #pragma unroll
        for (int e = 0; e < NE; e++) g_Cw[t * NE + e] = crow[e];
        #pragma unroll
        for (int i = 0; i < NTOPK; i++) {
            int e = inds[i];
            int posn = atomicAdd(&g_cnt[e], 1);
            g_bucket[e * NT + posn] = t;
        }
    }
}

// ---------------- elementwise combines ----------------
__global__ __launch_bounds__(256) void combine_expert_kernel()
{
    long stride = (long)gridDim.x * 256;
    for (int e = 0; e < NE; e++) {
        int cnt = g_cnt[e];
        long work = (long)cnt * EI;
        for (long idx = (long)blockIdx.x * 256 + threadIdx.x; idx < work; idx += stride) {
            int m = (int)(idx / EI);
            int tok = g_bucket[e * NT + m];
            float w = g_Cw[tok * NE + e];
            size_t o = ((size_t)e * NT + m) * EI + (idx % EI);
            float gv = g_eg[o], uv = g_eu[o];
            g_eg[o] = (gv / (1.f + expf(-gv))) * uv * w;
        }
    }
}

__global__ __launch_bounds__(256) void combine_shared_kernel()
{
    size_t idx = (size_t)blockIdx.x * 256 + threadIdx.x;
    if (idx >= (size_t)NT * SHI) return;
    float gv = g_sg[idx], uv = g_su[idx];
    g_sg[idx] = (gv / (1.f + expf(-gv))) * uv;
}

// ---------------- final: out = h1 + y ----------------
__global__ void final_add_kernel(float* __restrict__ out)
{
    int i = blockIdx.x * blockDim.x + threadIdx.x;
    if (i < NT * DMODEL) out[i] = g_h1[i] + g_y[i];
}

// ---------------- launch ----------------
extern "C" void kernel_launch(void* const* d_in, const int* in_sizes, int n_in,
                              void* d_out, int out_size)
{
    const float* x        = (const float*)d_in[0];
    const float* w_q      = (const float*)d_in[1];
    const float* w_k      = (const float*)d_in[2];
    const float* w_v      = (const float*)d_in[3];
    const float* w_o      = (const float*)d_in[4];
    const float* q_norm_w = (const float*)d_in[5];
    const float* k_norm_w = (const float*)d_in[6];
    const float* ln1_w    = (const float*)d_in[7];
    const float* ln2_w    = (const float*)d_in[8];
    const float* gate_w   = (const float*)d_in[9];
    const float* gate_b   = (const float*)d_in[10];
    const float* wg       = (const float*)d_in[11];
    const float* wu       = (const float*)d_in[12];
    const float* wd       = (const float*)d_in[13];
    const float* sh_g     = (const float*)d_in[14];
    const float* sh_u     = (const float*)d_in[15];
    const float* sh_d     = (const float*)d_in[16];
    float* out = (float*)d_out;

    static int attr_done = 0;
    if (!attr_done) {
        cudaFuncSetAttribute(qkv3_kernel,       cudaFuncAttributeMaxDynamicSharedMemorySize, GEMM_SMEM);
        cudaFuncSetAttribute(gemm3o_kernel,     cudaFuncAttributeMaxDynamicSharedMemorySize, GEMM_SMEM);
        cudaFuncSetAttribute(dense1_kernel,     cudaFuncAttributeMaxDynamicSharedMemorySize, GEMM_SMEM);
        cudaFuncSetAttribute(dense1_dual_kernel,cudaFuncAttributeMaxDynamicSharedMemorySize, GEMM_SMEM);
        cudaFuncSetAttribute(egu1_kernel,       cudaFuncAttributeMaxDynamicSharedMemorySize, GEMM_SMEM);
        cudaFuncSetAttribute(edown1_kernel,     cudaFuncAttributeMaxDynamicSharedMemorySize, GEMM_SMEM);
        attr_done = 1;
    }

    float *ph, *pq, *pk, *pattn, *ph1, *pt, *psg, *psu, *py;
    cudaGetSymbolAddress((void**)&ph,    g_h);
    cudaGetSymbolAddress((void**)&pq,    g_q);
    cudaGetSymbolAddress((void**)&pk,    g_k);
    cudaGetSymbolAddress((void**)&pattn, g_attn);
    cudaGetSymbolAddress((void**)&ph1,   g_h1);
    cudaGetSymbolAddress((void**)&pt,    g_t);
    cudaGetSymbolAddress((void**)&psg,   g_sg);
    cudaGetSymbolAddress((void**)&psu,   g_su);
    cudaGetSymbolAddress((void**)&py,    g_y);

    // 0. RoPE table
    rope_table_kernel<<<LSEQ, 64>>>();
    // 1. pre-attn norm
    rmsnorm_kernel<<<LSEQ, 256>>>(x, ln1_w, ph);
    // 2. fused QKV projection (3xTF32, pipelined)
    qkv3_kernel<<<dim3(24, 16), 256, GEMM_SMEM>>>(ph, w_q, w_k, w_v);
    // 3. q/k rmsnorm + rope
    qknorm_rope_kernel<<<LSEQ * NH, 128>>>(pq, q_norm_w, NH);
    qknorm_rope_kernel<<<LSEQ * NKVH, 128>>>(pk, k_norm_w, NKVH);
    // 4. attention (fp32)
    attn_kernel<<<dim3(LSEQ / 32, NH), 128>>>();
    // 5. output proj + residual (3xTF32)
    gemm3o_kernel<<<dim3(16, 16), 256, GEMM_SMEM>>>(pattn, w_o, ph1, x);
    // 6. post-attn norm
    rmsnorm_kernel<<<LSEQ, 256>>>(ph1, ln2_w, pt);
    // 7. routing (fp32, exact)
    zero_cnt_kernel<<<1, 32>>>();
    gate_kernel<<<NT, 256>>>(gate_w, gate_b);
    // 8. shared expert (1xTF32): gate+up in one launch, combine, down (STORES y)
    dense1_dual_kernel<<<dim3(SHI / 128, NT / 128, 2), 256, GEMM_SMEM>>>(
        pt, sh_g, sh_u, psg, psu, SHI, DMODEL);
    combine_shared_kernel<<<(int)(((size_t)NT * SHI + 255) / 256), 256>>>();
    dense1_kernel<<<dim3(DMODEL / 128, NT / 128), 256, GEMM_SMEM>>>(psg, sh_d, py, DMODEL, SHI);
    // 9. routed experts (1xTF32, gathered): gate+up in one launch, combine, down
    egu1_kernel<<<dim3(EI / 128, NT / 128, NE * 2), 256, GEMM_SMEM>>>(wg, wu);
    combine_expert_kernel<<<1184, 256>>>();
    edown1_kernel<<<dim3(DMODEL / 128, NT / 128, NE), 256, GEMM_SMEM>>>(wd);
    // 10. final residual add
    final_add_kernel<<<(NT * DMODEL + 255) / 256, 256>>>(out);
    (void)in_sizes; (void)n_in; (void)out_size;
}